// round 1
// baseline (speedup 1.0000x reference)
#include <cuda_runtime.h>
#include <cuda_bf16.h>

// ---------------- problem constants ----------------
#define NB    64      // batch
#define TD    99      // decode steps (T_DEC-1)
#define TENC  512
#define HD    512
#define KSZ   128
#define VSZ   128
#define VOC   32000

// predictions elements, then attention maps
#define PRED_ELEMS (202752000LL)   // 64*99*32000

// ---------------- device scratch (static, no runtime alloc) ----------------
__device__ float g_h1 [HD * NB];     // [feature][batch]
__device__ float g_c1 [HD * NB];
__device__ float g_h2 [KSZ * NB];
__device__ float g_c2 [KSZ * NB];
__device__ float g_ctx[VSZ * NB];
__device__ float g_part1[4][4 * HD][NB];    // LSTM1 gate partials (ksplit=4)
__device__ float g_part2[8][4 * KSZ][NB];   // LSTM2 gate partials (ksplit=8)
__device__ float g_X[NB * TD * 256];        // [n*99+t][256] = concat(h2, ctx)

__device__ __forceinline__ float sigf(float x) { return 1.0f / (1.0f + expf(-x)); }

// ---------------- init: zero recurrent state ----------------
__global__ void init_state() {
    int idx = blockIdx.x * blockDim.x + threadIdx.x;   // grid covers 64*512
    if (idx < HD * NB) { g_h1[idx] = 0.f; g_c1[idx] = 0.f; }
    if (idx < KSZ * NB) { g_h2[idx] = 0.f; g_c2[idx] = 0.f; g_ctx[idx] = 0.f; }
}

// ---------------- K1a: LSTM1 gates partial GEMM ----------------
// gates1[2048][64] partial over K chunk. K total = 1152:
//   k in [0,512): embedding[text[n][t]]
//   k in [512,640): context
//   k in [640,1152): h1
// grid (32 j-tiles of 16, 4 k-chunks of 288), 256 threads.
__global__ void __launch_bounds__(256) k1a(
    const float* __restrict__ emb, const int* __restrict__ text,
    const float* __restrict__ Wih1, const float* __restrict__ Whh1, int t)
{
    int jx = blockIdx.x;       // 0..31
    int ksp = blockIdx.y;      // 0..3
    int j0 = jx * 16;
    int kbase0 = ksp * 288;
    int tid = threadIdx.x;
    int nb = tid & 15, jg = tid >> 4;
    int n0 = nb * 4;

    float acc[4][4] = {};
    __shared__ float xs[32][64];
    __shared__ float ws[32][68];   // padded

    for (int kb = 0; kb < 288; kb += 32) {
        int kbase = kbase0 + kb;
        // xs[kk][n] : batch-fast, coalesced
        #pragma unroll
        for (int i = 0; i < 8; i++) {
            int lin = tid + i * 256;
            int kk = lin >> 6, nn = lin & 63;
            int k = kbase + kk;
            float v;
            if (k < 512)       v = emb[(long long)text[nn * 100 + t] * 512 + k];
            else if (k < 640)  v = g_ctx[(k - 512) * NB + nn];
            else               v = g_h1[(k - 640) * NB + nn];
            xs[kk][nn] = v;
        }
        // ws[kk][jj*4+gate] : k-fast global reads (coalesced row segments)
        #pragma unroll
        for (int i = 0; i < 8; i++) {
            int lin = tid + i * 256;
            int kk = lin & 31, c = lin >> 5;
            int jj = c >> 2, gate = c & 3;
            int grow = gate * 512 + j0 + jj;
            int k = kbase + kk;
            ws[kk][c] = (k < 640) ? Wih1[grow * 640 + k]
                                  : Whh1[grow * 512 + (k - 640)];
        }
        __syncthreads();
        #pragma unroll
        for (int kk = 0; kk < 32; kk++) {
            float4 xv = *(const float4*)&xs[kk][n0];
            float4 wv = *(const float4*)&ws[kk][jg * 4];
            float w4[4] = {wv.x, wv.y, wv.z, wv.w};
            float x4[4] = {xv.x, xv.y, xv.z, xv.w};
            #pragma unroll
            for (int g = 0; g < 4; g++)
                #pragma unroll
                for (int b = 0; b < 4; b++)
                    acc[g][b] += w4[g] * x4[b];
        }
        __syncthreads();
    }
    #pragma unroll
    for (int g = 0; g < 4; g++)
        *(float4*)&g_part1[ksp][g * 512 + j0 + jg][n0] =
            make_float4(acc[g][0], acc[g][1], acc[g][2], acc[g][3]);
}

// ---------------- K1b: LSTM1 reduce + activation ----------------
__global__ void __launch_bounds__(256) k1b(
    const float* __restrict__ bih1, const float* __restrict__ bhh1)
{
    int idx = blockIdx.x * blockDim.x + threadIdx.x;  // 0..32767
    int n = idx & 63, u = idx >> 6;                   // u < 512
    float gi = 0.f, gf = 0.f, gg = 0.f, go = 0.f;
    #pragma unroll
    for (int s = 0; s < 4; s++) {
        gi += g_part1[s][u][n];
        gf += g_part1[s][u + 512][n];
        gg += g_part1[s][u + 1024][n];
        go += g_part1[s][u + 1536][n];
    }
    gi += bih1[u] + bhh1[u];
    gf += bih1[u + 512] + bhh1[u + 512];
    gg += bih1[u + 1024] + bhh1[u + 1024];
    go += bih1[u + 1536] + bhh1[u + 1536];
    float c = g_c1[u * NB + n];
    float cn = sigf(gf) * c + sigf(gi) * tanhf(gg);
    float hn = sigf(go) * tanhf(cn);
    g_c1[u * NB + n] = cn;
    g_h1[u * NB + n] = hn;
}

// ---------------- K2a: LSTM2 gates partial GEMM ----------------
// gates2[512][64]: K = 640 (h1 512 + h2 128). grid (8 j-tiles, 8 k-chunks of 80).
__global__ void __launch_bounds__(256) k2a(
    const float* __restrict__ Wih2, const float* __restrict__ Whh2)
{
    int jx = blockIdx.x;        // 0..7
    int ksp = blockIdx.y;       // 0..7
    int j0 = jx * 16;
    int kbase0 = ksp * 80;
    int tid = threadIdx.x;
    int nb = tid & 15, jg = tid >> 4;
    int n0 = nb * 4;

    float acc[4][4] = {};
    __shared__ float xs[16][64];
    __shared__ float ws[16][68];

    for (int kb = 0; kb < 80; kb += 16) {
        int kbase = kbase0 + kb;
        #pragma unroll
        for (int i = 0; i < 4; i++) {
            int lin = tid + i * 256;
            int kk = lin >> 6, nn = lin & 63;
            int k = kbase + kk;
            xs[kk][nn] = (k < 512) ? g_h1[k * NB + nn]
                                   : g_h2[(k - 512) * NB + nn];
        }
        #pragma unroll
        for (int i = 0; i < 4; i++) {
            int lin = tid + i * 256;
            int kk = lin & 15, c = lin >> 4;
            int jj = c >> 2, gate = c & 3;
            int grow = gate * 128 + j0 + jj;
            int k = kbase + kk;
            ws[kk][c] = (k < 512) ? Wih2[grow * 512 + k]
                                  : Whh2[grow * 128 + (k - 512)];
        }
        __syncthreads();
        #pragma unroll
        for (int kk = 0; kk < 16; kk++) {
            float4 xv = *(const float4*)&xs[kk][n0];
            float4 wv = *(const float4*)&ws[kk][jg * 4];
            float w4[4] = {wv.x, wv.y, wv.z, wv.w};
            float x4[4] = {xv.x, xv.y, xv.z, xv.w};
            #pragma unroll
            for (int g = 0; g < 4; g++)
                #pragma unroll
                for (int b = 0; b < 4; b++)
                    acc[g][b] += w4[g] * x4[b];
        }
        __syncthreads();
    }
    #pragma unroll
    for (int g = 0; g < 4; g++)
        *(float4*)&g_part2[ksp][g * 128 + j0 + jg][n0] =
            make_float4(acc[g][0], acc[g][1], acc[g][2], acc[g][3]);
}

// ---------------- K3: LSTM2 activation + attention + context ----------------
// one block per batch element n; 256 threads.
__global__ void __launch_bounds__(256) k3(
    const float* __restrict__ enc_key, const float* __restrict__ values,
    const int* __restrict__ lens,
    const float* __restrict__ bih2, const float* __restrict__ bhh2,
    float* __restrict__ out, int t)
{
    int n = blockIdx.x;
    int tid = threadIdx.x;
    __shared__ float h2s[KSZ];
    __shared__ float attn[TENC];
    __shared__ float redA[8];
    __shared__ float redB[8];
    __shared__ float cred[VSZ];

    // ---- stage 1: gates2 reduce + LSTM2 cell update
    if (tid < KSZ) {
        int u = tid;
        float gi = 0.f, gf = 0.f, gg = 0.f, go = 0.f;
        #pragma unroll
        for (int s = 0; s < 8; s++) {
            gi += g_part2[s][u][n];
            gf += g_part2[s][u + 128][n];
            gg += g_part2[s][u + 256][n];
            go += g_part2[s][u + 384][n];
        }
        gi += bih2[u] + bhh2[u];
        gf += bih2[u + 128] + bhh2[u + 128];
        gg += bih2[u + 256] + bhh2[u + 256];
        go += bih2[u + 384] + bhh2[u + 384];
        float c = g_c2[u * NB + n];
        float cn = sigf(gf) * c + sigf(gi) * tanhf(gg);
        float hn = sigf(go) * tanhf(cn);
        g_c2[u * NB + n] = cn;
        g_h2[u * NB + n] = hn;
        h2s[u] = hn;
        g_X[((long long)n * TD + t) * 256 + u] = hn;
    }
    __syncthreads();

    int len = lens[n];

    // ---- stage 2: energies (each thread handles tau = tid and tid+256)
    float e[2];
    #pragma unroll
    for (int q = 0; q < 2; q++) {
        int tau = tid + q * 256;
        float s = -1e30f;
        if (tau < len) {
            s = 0.f;
            const float4* ek = (const float4*)(enc_key + ((long long)n * TENC + tau) * KSZ);
            const float4* hq = (const float4*)h2s;
            #pragma unroll 8
            for (int d = 0; d < 32; d++) {
                float4 kv = ek[d]; float4 hv = hq[d];
                s += kv.x * hv.x + kv.y * hv.y + kv.z * hv.z + kv.w * hv.w;
            }
        }
        e[q] = s;
    }

    // ---- stage 3: masked softmax (== softmax*mask/renorm in exact math)
    float m = fmaxf(e[0], e[1]);
    #pragma unroll
    for (int o = 16; o; o >>= 1) m = fmaxf(m, __shfl_xor_sync(0xffffffffu, m, o));
    if ((tid & 31) == 0) redA[tid >> 5] = m;
    __syncthreads();
    m = redA[0];
    #pragma unroll
    for (int w = 1; w < 8; w++) m = fmaxf(m, redA[w]);

    float p0 = (tid       < len) ? expf(e[0] - m) : 0.f;
    float p1 = (tid + 256 < len) ? expf(e[1] - m) : 0.f;
    float ssum = p0 + p1;
    #pragma unroll
    for (int o = 16; o; o >>= 1) ssum += __shfl_xor_sync(0xffffffffu, ssum, o);
    if ((tid & 31) == 0) redB[tid >> 5] = ssum;
    __syncthreads();
    float tot = redB[0];
    #pragma unroll
    for (int w = 1; w < 8; w++) tot += redB[w];
    float inv = 1.0f / tot;
    p0 *= inv; p1 *= inv;
    attn[tid] = p0;
    attn[tid + 256] = p1;
    long long ob = PRED_ELEMS + ((long long)n * TD + t) * TENC;
    out[ob + tid] = p0;
    out[ob + tid + 256] = p1;
    __syncthreads();

    // ---- stage 4: context = attn @ values[n]
    int v = tid & 127, half = tid >> 7;
    float s4 = 0.f;
    const float* vp = values + (long long)n * TENC * VSZ + v;
    int tb = half * 256;
    #pragma unroll 8
    for (int tau = tb; tau < tb + 256; tau++)
        s4 += attn[tau] * vp[(long long)tau * VSZ];
    if (half == 1) cred[v] = s4;
    __syncthreads();
    if (half == 0) {
        float cv = s4 + cred[v];
        g_ctx[v * NB + n] = cv;
        g_X[((long long)n * TD + t) * 256 + 128 + v] = cv;
    }
}

// ---------------- final GEMM: preds[6336][32000] = X @ Wout^T + bout ----------------
// 128x128 block tile, 8x8 per-thread micro tile, K chunks of 16.
__global__ void __launch_bounds__(256) gemm_out(
    const float* __restrict__ Wout, const float* __restrict__ bout,
    float* __restrict__ out)
{
    __shared__ float As[16][132];
    __shared__ float Bs[16][132];
    int bn = blockIdx.x;   // 0..249
    int bm = blockIdx.y;   // 0..49
    int tid = threadIdx.x;
    int tx = tid & 15, ty = tid >> 4;
    int m0 = ty * 8, n0 = tx * 8;
    float acc[8][8] = {};

    for (int kc = 0; kc < 256; kc += 16) {
        #pragma unroll
        for (int i = 0; i < 2; i++) {
            int lin = tid + i * 256;
            int ml = lin >> 2, kq = lin & 3;
            int row = bm * 128 + ml;
            float4 v = make_float4(0.f, 0.f, 0.f, 0.f);
            if (row < NB * TD)
                v = *(const float4*)&g_X[(long long)row * 256 + kc + kq * 4];
            As[kq * 4 + 0][ml] = v.x; As[kq * 4 + 1][ml] = v.y;
            As[kq * 4 + 2][ml] = v.z; As[kq * 4 + 3][ml] = v.w;
        }
        #pragma unroll
        for (int i = 0; i < 2; i++) {
            int lin = tid + i * 256;
            int vl = lin >> 2, kq = lin & 3;
            int col = bn * 128 + vl;
            float4 v = *(const float4*)&Wout[(long long)col * 256 + kc + kq * 4];
            Bs[kq * 4 + 0][vl] = v.x; Bs[kq * 4 + 1][vl] = v.y;
            Bs[kq * 4 + 2][vl] = v.z; Bs[kq * 4 + 3][vl] = v.w;
        }
        __syncthreads();
        #pragma unroll
        for (int kk = 0; kk < 16; kk++) {
            float4 a0 = *(const float4*)&As[kk][m0];
            float4 a1 = *(const float4*)&As[kk][m0 + 4];
            float4 b0 = *(const float4*)&Bs[kk][n0];
            float4 b1 = *(const float4*)&Bs[kk][n0 + 4];
            float a[8] = {a0.x, a0.y, a0.z, a0.w, a1.x, a1.y, a1.z, a1.w};
            float b[8] = {b0.x, b0.y, b0.z, b0.w, b1.x, b1.y, b1.z, b1.w};
            #pragma unroll
            for (int i = 0; i < 8; i++)
                #pragma unroll
                for (int j = 0; j < 8; j++)
                    acc[i][j] += a[i] * b[j];
        }
        __syncthreads();
    }

    float4 bv0 = *(const float4*)&bout[bn * 128 + n0];
    float4 bv1 = *(const float4*)&bout[bn * 128 + n0 + 4];
    float bb[8] = {bv0.x, bv0.y, bv0.z, bv0.w, bv1.x, bv1.y, bv1.z, bv1.w};
    #pragma unroll
    for (int i = 0; i < 8; i++) {
        int row = bm * 128 + m0 + i;
        if (row < NB * TD) {
            long long base = (long long)row * VOC + bn * 128 + n0;
            *(float4*)&out[base] = make_float4(acc[i][0] + bb[0], acc[i][1] + bb[1],
                                               acc[i][2] + bb[2], acc[i][3] + bb[3]);
            *(float4*)&out[base + 4] = make_float4(acc[i][4] + bb[4], acc[i][5] + bb[5],
                                                   acc[i][6] + bb[6], acc[i][7] + bb[7]);
        }
    }
}

// ---------------- launch ----------------
extern "C" void kernel_launch(void* const* d_in, const int* in_sizes, int n_in,
                              void* d_out, int out_size)
{
    (void)in_sizes; (void)n_in; (void)out_size;
    const float* enc_key   = (const float*)d_in[0];
    const float* values    = (const float*)d_in[1];
    const int*   lens      = (const int*)  d_in[2];
    const int*   text      = (const int*)  d_in[3];
    const float* embedding = (const float*)d_in[4];
    const float* Wih1      = (const float*)d_in[5];
    const float* Whh1      = (const float*)d_in[6];
    const float* bih1      = (const float*)d_in[7];
    const float* bhh1      = (const float*)d_in[8];
    const float* Wih2      = (const float*)d_in[9];
    const float* Whh2      = (const float*)d_in[10];
    const float* bih2      = (const float*)d_in[11];
    const float* bhh2      = (const float*)d_in[12];
    const float* Wout      = (const float*)d_in[13];
    const float* bout      = (const float*)d_in[14];
    float* out = (float*)d_out;

    init_state<<<128, 256>>>();
    for (int t = 0; t < TD; t++) {
        k1a<<<dim3(32, 4), 256>>>(embedding, text, Wih1, Whh1, t);
        k1b<<<128, 256>>>(bih1, bhh1);
        k2a<<<dim3(8, 8), 256>>>(Wih2, Whh2);
        k3<<<64, 256>>>(enc_key, values, lens, bih2, bhh2, out, t);
    }
    gemm_out<<<dim3(250, 50), 256>>>(Wout, bout, out);
}

// round 2
// speedup vs baseline: 1.0091x; 1.0091x over previous
#include <cuda_runtime.h>
#include <cuda_bf16.h>

// ---------------- problem constants ----------------
#define NB    64      // batch
#define TD    99      // decode steps (T_DEC-1)
#define TENC  512
#define HD    512
#define KSZ   128
#define VSZ   128
#define VOC   32000
#define NBLK  128     // persistent grid size (<= 148 SMs -> co-resident)

// predictions elements, then attention maps
#define PRED_ELEMS (202752000LL)   // 64*99*32000

// ---------------- device scratch (static, no runtime alloc) ----------------
__device__ float g_h1 [HD * NB];     // [feature][batch]
__device__ float g_c1 [HD * NB];
__device__ float g_h2 [KSZ * NB];
__device__ float g_c2 [KSZ * NB];
__device__ float g_ctx[VSZ * NB];
__device__ float g_part1[4][4 * HD][NB];    // LSTM1 gate partials (ksplit=4)
__device__ float g_part2[8][4 * KSZ][NB];   // LSTM2 gate partials (ksplit=8)
__device__ float g_X[NB * TD * 256];        // [n*99+t][256] = concat(h2, ctx)

__device__ unsigned g_cnt;   // barrier arrival counter (always returns to 0)
__device__ unsigned g_gen;   // barrier generation (monotonic across launches)

__device__ __forceinline__ float sigf(float x) { return 1.0f / (1.0f + expf(-x)); }

// ---------------- software grid barrier ----------------
// gen is thread-0's local copy of g_gen. __threadfence (gpu scope) emits
// CCTL.IVALL on sm_103a: publishes stores AND invalidates this SM's L1D so
// post-barrier loads see other SMs' writes.
__device__ __forceinline__ void gridsync(unsigned &gen) {
    __syncthreads();
    if (threadIdx.x == 0) {
        __threadfence();
        unsigned t = atomicAdd(&g_cnt, 1);
        if (t == NBLK - 1) {
            atomicExch(&g_cnt, 0);
            __threadfence();
            atomicAdd(&g_gen, 1);
        } else {
            while (atomicAdd(&g_gen, 0) == gen) __nanosleep(64);
        }
        gen++;
        __threadfence();
    }
    __syncthreads();
}

// ---------------- persistent recurrence kernel ----------------
__global__ void __launch_bounds__(256) decoder_persist(
    const float* __restrict__ enc_key, const float* __restrict__ values,
    const int* __restrict__ lens, const int* __restrict__ text,
    const float* __restrict__ emb,
    const float* __restrict__ Wih1, const float* __restrict__ Whh1,
    const float* __restrict__ bih1, const float* __restrict__ bhh1,
    const float* __restrict__ Wih2, const float* __restrict__ Whh2,
    const float* __restrict__ bih2, const float* __restrict__ bhh2,
    float* __restrict__ out)
{
    const int bx = blockIdx.x;
    const int tid = threadIdx.x;

    unsigned gen = 0;
    if (tid == 0) gen = atomicAdd(&g_gen, 0);   // carry across graph replays

    // shared memory (phases are separated by gridsync -> safe to reuse)
    __shared__ float xs1[32][64];
    __shared__ float ws1[32][68];
    __shared__ float xs2[16][64];
    __shared__ float ws2[16][68];
    __shared__ float h2s[KSZ];
    __shared__ float attn[TENC];
    __shared__ float redA[8];
    __shared__ float redB[8];
    __shared__ float cred[VSZ];

    // ---- init recurrent state ----
    {
        int i = bx * 256 + tid;                 // exactly covers 32768
        g_h1[i] = 0.f; g_c1[i] = 0.f;
        if (i < KSZ * NB) { g_h2[i] = 0.f; g_c2[i] = 0.f; g_ctx[i] = 0.f; }
    }
    gridsync(gen);

    for (int t = 0; t < TD; t++) {
        // ================= phase 1a: LSTM1 gates partial GEMM =================
        // block bx: jx = bx&31 (16 units), ksp = bx>>5 (K chunk of 288)
        {
            int jx = bx & 31, ksp = bx >> 5;
            int j0 = jx * 16;
            int kbase0 = ksp * 288;
            int nb = tid & 15, jg = tid >> 4;
            int n0 = nb * 4;
            float acc[4][4] = {};

            for (int kb = 0; kb < 288; kb += 32) {
                int kbase = kbase0 + kb;
                #pragma unroll
                for (int i = 0; i < 8; i++) {
                    int lin = tid + i * 256;
                    int kk = lin >> 6, nn = lin & 63;
                    int k = kbase + kk;
                    float v;
                    if (k < 512)       v = emb[(long long)text[nn * 100 + t] * 512 + k];
                    else if (k < 640)  v = g_ctx[(k - 512) * NB + nn];
                    else               v = g_h1[(k - 640) * NB + nn];
                    xs1[kk][nn] = v;
                }
                #pragma unroll
                for (int i = 0; i < 8; i++) {
                    int lin = tid + i * 256;
                    int kk = lin & 31, c = lin >> 5;
                    int jj = c >> 2, gate = c & 3;
                    int grow = gate * 512 + j0 + jj;
                    int k = kbase + kk;
                    ws1[kk][c] = (k < 640) ? Wih1[grow * 640 + k]
                                           : Whh1[grow * 512 + (k - 640)];
                }
                __syncthreads();
                #pragma unroll
                for (int kk = 0; kk < 32; kk++) {
                    float4 xv = *(const float4*)&xs1[kk][n0];
                    float4 wv = *(const float4*)&ws1[kk][jg * 4];
                    float w4[4] = {wv.x, wv.y, wv.z, wv.w};
                    float x4[4] = {xv.x, xv.y, xv.z, xv.w};
                    #pragma unroll
                    for (int g = 0; g < 4; g++)
                        #pragma unroll
                        for (int b = 0; b < 4; b++)
                            acc[g][b] += w4[g] * x4[b];
                }
                __syncthreads();
            }
            #pragma unroll
            for (int g = 0; g < 4; g++)
                *(float4*)&g_part1[ksp][g * 512 + j0 + jg][n0] =
                    make_float4(acc[g][0], acc[g][1], acc[g][2], acc[g][3]);
        }
        gridsync(gen);

        // ================= phase 1b: LSTM1 reduce + cell update =================
        {
            int idx = bx * 256 + tid;          // 32768 = 512 units x 64 batch
            int n = idx & 63, u = idx >> 6;
            float gi = 0.f, gf = 0.f, gg = 0.f, go = 0.f;
            #pragma unroll
            for (int s = 0; s < 4; s++) {
                gi += g_part1[s][u][n];
                gf += g_part1[s][u + 512][n];
                gg += g_part1[s][u + 1024][n];
                go += g_part1[s][u + 1536][n];
            }
            gi += bih1[u] + bhh1[u];
            gf += bih1[u + 512] + bhh1[u + 512];
            gg += bih1[u + 1024] + bhh1[u + 1024];
            go += bih1[u + 1536] + bhh1[u + 1536];
            float c = g_c1[u * NB + n];
            float cn = sigf(gf) * c + sigf(gi) * tanhf(gg);
            float hn = sigf(go) * tanhf(cn);
            g_c1[u * NB + n] = cn;
            g_h1[u * NB + n] = hn;
        }
        gridsync(gen);

        // ================= phase 2a: LSTM2 gates partial GEMM =================
        if (bx < 64) {
            int jx = bx & 7, ksp = bx >> 3;
            int j0 = jx * 16;
            int kbase0 = ksp * 80;
            int nb = tid & 15, jg = tid >> 4;
            int n0 = nb * 4;
            float acc[4][4] = {};

            for (int kb = 0; kb < 80; kb += 16) {
                int kbase = kbase0 + kb;
                #pragma unroll
                for (int i = 0; i < 4; i++) {
                    int lin = tid + i * 256;
                    int kk = lin >> 6, nn = lin & 63;
                    int k = kbase + kk;
                    xs2[kk][nn] = (k < 512) ? g_h1[k * NB + nn]
                                            : g_h2[(k - 512) * NB + nn];
                }
                #pragma unroll
                for (int i = 0; i < 4; i++) {
                    int lin = tid + i * 256;
                    int kk = lin & 15, c = lin >> 4;
                    int jj = c >> 2, gate = c & 3;
                    int grow = gate * 128 + j0 + jj;
                    int k = kbase + kk;
                    ws2[kk][c] = (k < 512) ? Wih2[grow * 512 + k]
                                           : Whh2[grow * 128 + (k - 512)];
                }
                __syncthreads();
                #pragma unroll
                for (int kk = 0; kk < 16; kk++) {
                    float4 xv = *(const float4*)&xs2[kk][n0];
                    float4 wv = *(const float4*)&ws2[kk][jg * 4];
                    float w4[4] = {wv.x, wv.y, wv.z, wv.w};
                    float x4[4] = {xv.x, xv.y, xv.z, xv.w};
                    #pragma unroll
                    for (int g = 0; g < 4; g++)
                        #pragma unroll
                        for (int b = 0; b < 4; b++)
                            acc[g][b] += w4[g] * x4[b];
                }
                __syncthreads();
            }
            #pragma unroll
            for (int g = 0; g < 4; g++)
                *(float4*)&g_part2[ksp][g * 128 + j0 + jg][n0] =
                    make_float4(acc[g][0], acc[g][1], acc[g][2], acc[g][3]);
        }
        gridsync(gen);

        // ========== phase 3: LSTM2 cell + attention + context (block = batch n) ==========
        if (bx < 64) {
            int n = bx;

            if (tid < KSZ) {
                int u = tid;
                float gi = 0.f, gf = 0.f, gg = 0.f, go = 0.f;
                #pragma unroll
                for (int s = 0; s < 8; s++) {
                    gi += g_part2[s][u][n];
                    gf += g_part2[s][u + 128][n];
                    gg += g_part2[s][u + 256][n];
                    go += g_part2[s][u + 384][n];
                }
                gi += bih2[u] + bhh2[u];
                gf += bih2[u + 128] + bhh2[u + 128];
                gg += bih2[u + 256] + bhh2[u + 256];
                go += bih2[u + 384] + bhh2[u + 384];
                float c = g_c2[u * NB + n];
                float cn = sigf(gf) * c + sigf(gi) * tanhf(gg);
                float hn = sigf(go) * tanhf(cn);
                g_c2[u * NB + n] = cn;
                g_h2[u * NB + n] = hn;
                h2s[u] = hn;
                g_X[((long long)n * TD + t) * 256 + u] = hn;
            }
            __syncthreads();

            int len = lens[n];

            float e[2];
            #pragma unroll
            for (int q = 0; q < 2; q++) {
                int tau = tid + q * 256;
                float s = -1e30f;
                if (tau < len) {
                    s = 0.f;
                    const float4* ek = (const float4*)(enc_key + ((long long)n * TENC + tau) * KSZ);
                    const float4* hq = (const float4*)h2s;
                    #pragma unroll 8
                    for (int d = 0; d < 32; d++) {
                        float4 kv = ek[d]; float4 hv = hq[d];
                        s += kv.x * hv.x + kv.y * hv.y + kv.z * hv.z + kv.w * hv.w;
                    }
                }
                e[q] = s;
            }

            float m = fmaxf(e[0], e[1]);
            #pragma unroll
            for (int o = 16; o; o >>= 1) m = fmaxf(m, __shfl_xor_sync(0xffffffffu, m, o));
            if ((tid & 31) == 0) redA[tid >> 5] = m;
            __syncthreads();
            m = redA[0];
            #pragma unroll
            for (int w = 1; w < 8; w++) m = fmaxf(m, redA[w]);

            float p0 = (tid       < len) ? expf(e[0] - m) : 0.f;
            float p1 = (tid + 256 < len) ? expf(e[1] - m) : 0.f;
            float ssum = p0 + p1;
            #pragma unroll
            for (int o = 16; o; o >>= 1) ssum += __shfl_xor_sync(0xffffffffu, ssum, o);
            if ((tid & 31) == 0) redB[tid >> 5] = ssum;
            __syncthreads();
            float tot = redB[0];
            #pragma unroll
            for (int w = 1; w < 8; w++) tot += redB[w];
            float inv = 1.0f / tot;
            p0 *= inv; p1 *= inv;
            attn[tid] = p0;
            attn[tid + 256] = p1;
            long long ob = PRED_ELEMS + ((long long)n * TD + t) * TENC;
            out[ob + tid] = p0;
            out[ob + tid + 256] = p1;
            __syncthreads();

            int v = tid & 127, half = tid >> 7;
            float s4 = 0.f;
            const float* vp = values + (long long)n * TENC * VSZ + v;
            int tb = half * 256;
            #pragma unroll 8
            for (int tau = tb; tau < tb + 256; tau++)
                s4 += attn[tau] * vp[(long long)tau * VSZ];
            if (half == 1) cred[v] = s4;
            __syncthreads();
            if (half == 0) {
                float cv = s4 + cred[v];
                g_ctx[v * NB + n] = cv;
                g_X[((long long)n * TD + t) * 256 + 128 + v] = cv;
            }
        }
        gridsync(gen);
    }
}

// ---------------- final GEMM: preds[6336][32000] = X @ Wout^T + bout ----------------
__global__ void __launch_bounds__(256) gemm_out(
    const float* __restrict__ Wout, const float* __restrict__ bout,
    float* __restrict__ out)
{
    __shared__ float As[16][132];
    __shared__ float Bs[16][132];
    int bn = blockIdx.x;   // 0..249
    int bm = blockIdx.y;   // 0..49
    int tid = threadIdx.x;
    int tx = tid & 15, ty = tid >> 4;
    int m0 = ty * 8, n0 = tx * 8;
    float acc[8][8] = {};

    for (int kc = 0; kc < 256; kc += 16) {
        #pragma unroll
        for (int i = 0; i < 2; i++) {
            int lin = tid + i * 256;
            int ml = lin >> 2, kq = lin & 3;
            int row = bm * 128 + ml;
            float4 v = make_float4(0.f, 0.f, 0.f, 0.f);
            if (row < NB * TD)
                v = *(const float4*)&g_X[(long long)row * 256 + kc + kq * 4];
            As[kq * 4 + 0][ml] = v.x; As[kq * 4 + 1][ml] = v.y;
            As[kq * 4 + 2][ml] = v.z; As[kq * 4 + 3][ml] = v.w;
        }
        #pragma unroll
        for (int i = 0; i < 2; i++) {
            int lin = tid + i * 256;
            int vl = lin >> 2, kq = lin & 3;
            int col = bn * 128 + vl;
            float4 v = *(const float4*)&Wout[(long long)col * 256 + kc + kq * 4];
            Bs[kq * 4 + 0][vl] = v.x; Bs[kq * 4 + 1][vl] = v.y;
            Bs[kq * 4 + 2][vl] = v.z; Bs[kq * 4 + 3][vl] = v.w;
        }
        __syncthreads();
        #pragma unroll
        for (int kk = 0; kk < 16; kk++) {
            float4 a0 = *(const float4*)&As[kk][m0];
            float4 a1 = *(const float4*)&As[kk][m0 + 4];
            float4 b0 = *(const float4*)&Bs[kk][n0];
            float4 b1 = *(const float4*)&Bs[kk][n0 + 4];
            float a[8] = {a0.x, a0.y, a0.z, a0.w, a1.x, a1.y, a1.z, a1.w};
            float b[8] = {b0.x, b0.y, b0.z, b0.w, b1.x, b1.y, b1.z, b1.w};
            #pragma unroll
            for (int i = 0; i < 8; i++)
                #pragma unroll
                for (int j = 0; j < 8; j++)
                    acc[i][j] += a[i] * b[j];
        }
        __syncthreads();
    }

    float4 bv0 = *(const float4*)&bout[bn * 128 + n0];
    float4 bv1 = *(const float4*)&bout[bn * 128 + n0 + 4];
    float bb[8] = {bv0.x, bv0.y, bv0.z, bv0.w, bv1.x, bv1.y, bv1.z, bv1.w};
    #pragma unroll
    for (int i = 0; i < 8; i++) {
        int row = bm * 128 + m0 + i;
        if (row < NB * TD) {
            long long base = (long long)row * VOC + bn * 128 + n0;
            *(float4*)&out[base] = make_float4(acc[i][0] + bb[0], acc[i][1] + bb[1],
                                               acc[i][2] + bb[2], acc[i][3] + bb[3]);
            *(float4*)&out[base + 4] = make_float4(acc[i][4] + bb[4], acc[i][5] + bb[5],
                                                   acc[i][6] + bb[6], acc[i][7] + bb[7]);
        }
    }
}

// ---------------- launch ----------------
extern "C" void kernel_launch(void* const* d_in, const int* in_sizes, int n_in,
                              void* d_out, int out_size)
{
    (void)in_sizes; (void)n_in; (void)out_size;
    const float* enc_key   = (const float*)d_in[0];
    const float* values    = (const float*)d_in[1];
    const int*   lens      = (const int*)  d_in[2];
    const int*   text      = (const int*)  d_in[3];
    const float* embedding = (const float*)d_in[4];
    const float* Wih1      = (const float*)d_in[5];
    const float* Whh1      = (const float*)d_in[6];
    const float* bih1      = (const float*)d_in[7];
    const float* bhh1      = (const float*)d_in[8];
    const float* Wih2      = (const float*)d_in[9];
    const float* Whh2      = (const float*)d_in[10];
    const float* bih2      = (const float*)d_in[11];
    const float* bhh2      = (const float*)d_in[12];
    const float* Wout      = (const float*)d_in[13];
    const float* bout      = (const float*)d_in[14];
    float* out = (float*)d_out;

    decoder_persist<<<NBLK, 256>>>(enc_key, values, lens, text, embedding,
                                   Wih1, Whh1, bih1, bhh1,
                                   Wih2, Whh2, bih2, bhh2, out);
    gemm_out<<<dim3(250, 50), 256>>>(Wout, bout, out);
}

// round 5
// speedup vs baseline: 1.1825x; 1.1718x over previous
#include <cuda_runtime.h>
#include <cuda_bf16.h>
#include <cstdint>

// ---------------- problem constants ----------------
#define NB    64      // batch
#define TD    99      // decode steps (T_DEC-1)
#define TENC  512
#define HD    512
#define KSZ   128
#define VSZ   128
#define VOC   32000
#define NBLK  128     // persistent grid size (<= 148 SMs -> co-resident)

#define PRED_ELEMS (202752000LL)   // 64*99*32000
#define MROWS 6336                 // NB*TD
#define MPAD  6400                 // padded to 50*128

// ---------------- device scratch (static, no runtime alloc) ----------------
__device__ float g_h1 [HD * NB];     // [feature][batch]
__device__ float g_c1 [HD * NB];
__device__ float g_h2 [KSZ * NB];
__device__ float g_c2 [KSZ * NB];
__device__ float g_ctx[VSZ * NB];
__device__ float g_embt[HD * NB];           // gathered embeddings, [k][n]
__device__ float g_part1[4][4 * HD][NB];    // LSTM1 gate partials (ksplit=4)
__device__ float g_part2[8][4 * KSZ][NB];   // LSTM2 gate partials (ksplit=8)
__device__ float g_X[NB * TD * 256];        // [n*99+t][256] = concat(h2, ctx)

// bf16 split operands for output GEMM (K=768: [Ah|Al|Ah] x [Bh|Bh|Bl])
__device__ __nv_bfloat16 g_A3[(size_t)MPAD * 768];
__device__ __nv_bfloat16 g_B3[(size_t)VOC * 768];

__device__ unsigned g_cnt;
__device__ unsigned g_gen;

__device__ __forceinline__ float sigf(float x) { return 1.0f / (1.0f + expf(-x)); }

__device__ __forceinline__ uint32_t smem_u32(const void* p) {
    uint32_t a;
    asm("{ .reg .u64 t; cvta.to.shared.u64 t, %1; cvt.u32.u64 %0, t; }" : "=r"(a) : "l"(p));
    return a;
}

// ---------------- software grid barrier ----------------
__device__ __forceinline__ void gridsync(unsigned &gen) {
    __syncthreads();
    if (threadIdx.x == 0) {
        __threadfence();
        unsigned t = atomicAdd(&g_cnt, 1);
        if (t == NBLK - 1) {
            atomicExch(&g_cnt, 0);
            __threadfence();
            atomicAdd(&g_gen, 1);
        } else {
            while (atomicAdd(&g_gen, 0) == gen) __nanosleep(64);
        }
        gen++;
        __threadfence();
    }
    __syncthreads();
}

// ---------------- persistent recurrence kernel ----------------
__global__ void __launch_bounds__(256) decoder_persist(
    const float* __restrict__ enc_key, const float* __restrict__ values,
    const int* __restrict__ lens, const int* __restrict__ text,
    const float* __restrict__ emb,
    const float* __restrict__ Wih1, const float* __restrict__ Whh1,
    const float* __restrict__ bih1, const float* __restrict__ bhh1,
    const float* __restrict__ Wih2, const float* __restrict__ Whh2,
    const float* __restrict__ bih2, const float* __restrict__ bhh2,
    float* __restrict__ out)
{
    const int bx = blockIdx.x;
    const int tid = threadIdx.x;

    unsigned gen = 0;
    if (tid == 0) gen = atomicAdd(&g_gen, 0);

    __shared__ float xs1[32][64];
    __shared__ float ws1[32][68];
    __shared__ float xs2[16][64];
    __shared__ float ws2[16][68];
    __shared__ float h2s[KSZ];
    __shared__ float attn[TENC];
    __shared__ float redA[8];
    __shared__ float redB[8];
    __shared__ float cred[VSZ];

    // ---- init: blocks 0-63 zero state, blocks 64-127 gather embeddings t=0
    if (bx < 64) {
        #pragma unroll
        for (int j = 0; j < 2; j++) {
            int idx = (bx * 256 + tid) + j * 16384;
            g_h1[idx] = 0.f; g_c1[idx] = 0.f;
            if (idx < KSZ * NB) { g_h2[idx] = 0.f; g_c2[idx] = 0.f; g_ctx[idx] = 0.f; }
        }
    } else {
        int idx = (bx - 64) * 256 + tid;
        if (idx < 8192) {
            int k4 = idx & 127, n = idx >> 7;
            const float4 e = *(const float4*)&emb[(long long)text[n * 100 + 0] * 512 + k4 * 4];
            g_embt[(k4 * 4 + 0) * 64 + n] = e.x;
            g_embt[(k4 * 4 + 1) * 64 + n] = e.y;
            g_embt[(k4 * 4 + 2) * 64 + n] = e.z;
            g_embt[(k4 * 4 + 3) * 64 + n] = e.w;
        }
    }
    gridsync(gen);

    for (int t = 0; t < TD; t++) {
        // ================= phase 1a: LSTM1 gates partial GEMM =================
        {
            int jx = bx & 31, ksp = bx >> 5;
            int j0 = jx * 16;
            int kbase0 = ksp * 288;
            int nb = tid & 15, jg = tid >> 4;
            int n0 = nb * 4;
            float acc[4][4] = {};

            for (int kb = 0; kb < 288; kb += 32) {
                int kbase = kbase0 + kb;
                // xs: [k][n] coalesced scalar loads (all sources batch-major)
                #pragma unroll
                for (int i = 0; i < 8; i++) {
                    int lin = tid + i * 256;
                    int kk = lin >> 6, nn = lin & 63;
                    int k = kbase + kk;
                    float v;
                    if (k < 512)       v = g_embt[k * 64 + nn];
                    else if (k < 640)  v = g_ctx[(k - 512) * NB + nn];
                    else               v = g_h1[(k - 640) * NB + nn];
                    xs1[kk][nn] = v;
                }
                // ws: float4 along k (4x fewer LDG)
                #pragma unroll
                for (int i = 0; i < 2; i++) {
                    int lin = tid + i * 256;          // 0..511
                    int kk4 = lin & 7;
                    int c = lin >> 3;                 // jj*4+gate
                    int jj = c >> 2, gate = c & 3;
                    int grow = gate * 512 + j0 + jj;
                    int k = kbase + kk4 * 4;
                    float4 w = (k < 640) ? *(const float4*)&Wih1[grow * 640 + k]
                                         : *(const float4*)&Whh1[grow * 512 + (k - 640)];
                    ws1[kk4 * 4 + 0][c] = w.x; ws1[kk4 * 4 + 1][c] = w.y;
                    ws1[kk4 * 4 + 2][c] = w.z; ws1[kk4 * 4 + 3][c] = w.w;
                }
                __syncthreads();
                #pragma unroll
                for (int kk = 0; kk < 32; kk++) {
                    float4 xv = *(const float4*)&xs1[kk][n0];
                    float4 wv = *(const float4*)&ws1[kk][jg * 4];
                    float w4[4] = {wv.x, wv.y, wv.z, wv.w};
                    float x4[4] = {xv.x, xv.y, xv.z, xv.w};
                    #pragma unroll
                    for (int g = 0; g < 4; g++)
                        #pragma unroll
                        for (int b = 0; b < 4; b++)
                            acc[g][b] += w4[g] * x4[b];
                }
                __syncthreads();
            }
            #pragma unroll
            for (int g = 0; g < 4; g++)
                *(float4*)&g_part1[ksp][g * 512 + j0 + jg][n0] =
                    make_float4(acc[g][0], acc[g][1], acc[g][2], acc[g][3]);
        }
        gridsync(gen);

        // ================= phase 1b: LSTM1 reduce + cell update =================
        {
            int idx = bx * 256 + tid;
            int n = idx & 63, u = idx >> 6;
            float gi = 0.f, gf = 0.f, gg = 0.f, go = 0.f;
            #pragma unroll
            for (int s = 0; s < 4; s++) {
                gi += g_part1[s][u][n];
                gf += g_part1[s][u + 512][n];
                gg += g_part1[s][u + 1024][n];
                go += g_part1[s][u + 1536][n];
            }
            gi += bih1[u] + bhh1[u];
            gf += bih1[u + 512] + bhh1[u + 512];
            gg += bih1[u + 1024] + bhh1[u + 1024];
            go += bih1[u + 1536] + bhh1[u + 1536];
            float c = g_c1[u * NB + n];
            float cn = sigf(gf) * c + sigf(gi) * tanhf(gg);
            float hn = sigf(go) * tanhf(cn);
            g_c1[u * NB + n] = cn;
            g_h1[u * NB + n] = hn;
        }
        gridsync(gen);

        // ================= phase 2a: LSTM2 gates partial GEMM =================
        if (bx < 64) {
            int jx = bx & 7, ksp = bx >> 3;
            int j0 = jx * 16;
            int kbase0 = ksp * 80;
            int nb = tid & 15, jg = tid >> 4;
            int n0 = nb * 4;
            float acc[4][4] = {};

            for (int kb = 0; kb < 80; kb += 16) {
                int kbase = kbase0 + kb;
                #pragma unroll
                for (int i = 0; i < 4; i++) {
                    int lin = tid + i * 256;
                    int kk = lin >> 6, nn = lin & 63;
                    int k = kbase + kk;
                    xs2[kk][nn] = (k < 512) ? g_h1[k * NB + nn]
                                            : g_h2[(k - 512) * NB + nn];
                }
                {
                    int kk4 = tid & 3;
                    int c = tid >> 2;                  // 0..63
                    int jj = c >> 2, gate = c & 3;
                    int grow = gate * 128 + j0 + jj;
                    int k = kbase + kk4 * 4;
                    float4 w = (k < 512) ? *(const float4*)&Wih2[grow * 512 + k]
                                         : *(const float4*)&Whh2[grow * 128 + (k - 512)];
                    ws2[kk4 * 4 + 0][c] = w.x; ws2[kk4 * 4 + 1][c] = w.y;
                    ws2[kk4 * 4 + 2][c] = w.z; ws2[kk4 * 4 + 3][c] = w.w;
                }
                __syncthreads();
                #pragma unroll
                for (int kk = 0; kk < 16; kk++) {
                    float4 xv = *(const float4*)&xs2[kk][n0];
                    float4 wv = *(const float4*)&ws2[kk][jg * 4];
                    float w4[4] = {wv.x, wv.y, wv.z, wv.w};
                    float x4[4] = {xv.x, xv.y, xv.z, xv.w};
                    #pragma unroll
                    for (int g = 0; g < 4; g++)
                        #pragma unroll
                        for (int b = 0; b < 4; b++)
                            acc[g][b] += w4[g] * x4[b];
                }
                __syncthreads();
            }
            #pragma unroll
            for (int g = 0; g < 4; g++)
                *(float4*)&g_part2[ksp][g * 128 + j0 + jg][n0] =
                    make_float4(acc[g][0], acc[g][1], acc[g][2], acc[g][3]);
        }
        gridsync(gen);

        // ========== phase 3: LSTM2 cell + attention + context (blocks 0-63) ==========
        if (bx < 64) {
            int n = bx;

            if (tid < KSZ) {
                int u = tid;
                float gi = 0.f, gf = 0.f, gg = 0.f, go = 0.f;
                #pragma unroll
                for (int s = 0; s < 8; s++) {
                    gi += g_part2[s][u][n];
                    gf += g_part2[s][u + 128][n];
                    gg += g_part2[s][u + 256][n];
                    go += g_part2[s][u + 384][n];
                }
                gi += bih2[u] + bhh2[u];
                gf += bih2[u + 128] + bhh2[u + 128];
                gg += bih2[u + 256] + bhh2[u + 256];
                go += bih2[u + 384] + bhh2[u + 384];
                float c = g_c2[u * NB + n];
                float cn = sigf(gf) * c + sigf(gi) * tanhf(gg);
                float hn = sigf(go) * tanhf(cn);
                g_c2[u * NB + n] = cn;
                g_h2[u * NB + n] = hn;
                h2s[u] = hn;
                g_X[((long long)n * TD + t) * 256 + u] = hn;
            }
            __syncthreads();

            int len = lens[n];

            float e[2];
            #pragma unroll
            for (int q = 0; q < 2; q++) {
                int tau = tid + q * 256;
                float s = -1e30f;
                if (tau < len) {
                    s = 0.f;
                    const float4* ek = (const float4*)(enc_key + ((long long)n * TENC + tau) * KSZ);
                    const float4* hq = (const float4*)h2s;
                    #pragma unroll 8
                    for (int d = 0; d < 32; d++) {
                        float4 kv = ek[d]; float4 hv = hq[d];
                        s += kv.x * hv.x + kv.y * hv.y + kv.z * hv.z + kv.w * hv.w;
                    }
                }
                e[q] = s;
            }

            float m = fmaxf(e[0], e[1]);
            #pragma unroll
            for (int o = 16; o; o >>= 1) m = fmaxf(m, __shfl_xor_sync(0xffffffffu, m, o));
            if ((tid & 31) == 0) redA[tid >> 5] = m;
            __syncthreads();
            m = redA[0];
            #pragma unroll
            for (int w = 1; w < 8; w++) m = fmaxf(m, redA[w]);

            float p0 = (tid       < len) ? expf(e[0] - m) : 0.f;
            float p1 = (tid + 256 < len) ? expf(e[1] - m) : 0.f;
            float ssum = p0 + p1;
            #pragma unroll
            for (int o = 16; o; o >>= 1) ssum += __shfl_xor_sync(0xffffffffu, ssum, o);
            if ((tid & 31) == 0) redB[tid >> 5] = ssum;
            __syncthreads();
            float tot = redB[0];
            #pragma unroll
            for (int w = 1; w < 8; w++) tot += redB[w];
            float inv = 1.0f / tot;
            p0 *= inv; p1 *= inv;
            attn[tid] = p0;
            attn[tid + 256] = p1;
            long long ob = PRED_ELEMS + ((long long)n * TD + t) * TENC;
            out[ob + tid] = p0;
            out[ob + tid + 256] = p1;
            __syncthreads();

            int v = tid & 127, half = tid >> 7;
            float s4 = 0.f;
            const float* vp = values + (long long)n * TENC * VSZ + v;
            int tb = half * 256;
            #pragma unroll 8
            for (int tau = tb; tau < tb + 256; tau++)
                s4 += attn[tau] * vp[(long long)tau * VSZ];
            if (half == 1) cred[v] = s4;
            __syncthreads();
            if (half == 0) {
                float cv = s4 + cred[v];
                g_ctx[v * NB + n] = cv;
                g_X[((long long)n * TD + t) * 256 + 128 + v] = cv;
            }
        } else if (t + 1 < TD) {
            // blocks 64-127: gather embeddings for step t+1 (free overlap)
            int idx = (bx - 64) * 256 + tid;
            if (idx < 8192) {
                int k4 = idx & 127, n = idx >> 7;
                const float4 e = *(const float4*)&emb[(long long)text[n * 100 + (t + 1)] * 512 + k4 * 4];
                g_embt[(k4 * 4 + 0) * 64 + n] = e.x;
                g_embt[(k4 * 4 + 1) * 64 + n] = e.y;
                g_embt[(k4 * 4 + 2) * 64 + n] = e.z;
                g_embt[(k4 * 4 + 3) * 64 + n] = e.w;
            }
        }
        gridsync(gen);
    }
}

// ---------------- bf16 split conversion kernels ----------------
__global__ void __launch_bounds__(256) convB(const float* __restrict__ W) {
    int i = blockIdx.x * 256 + threadIdx.x;          // < 2,048,000 (32000*64)
    float4 v = ((const float4*)W)[i];
    int row = i >> 6;
    int k = (i & 63) << 2;
    __nv_bfloat16* dst = g_B3 + (size_t)row * 768 + k;
    float xs[4] = {v.x, v.y, v.z, v.w};
    __align__(8) __nv_bfloat16 hi[4];
    __align__(8) __nv_bfloat16 lo[4];
    #pragma unroll
    for (int q = 0; q < 4; q++) {
        hi[q] = __float2bfloat16(xs[q]);
        lo[q] = __float2bfloat16(xs[q] - __bfloat162float(hi[q]));
    }
    *(uint2*)(dst)       = *(uint2*)hi;
    *(uint2*)(dst + 256) = *(uint2*)hi;
    *(uint2*)(dst + 512) = *(uint2*)lo;
}

__global__ void __launch_bounds__(256) convA() {
    int i = blockIdx.x * 256 + threadIdx.x;          // < 409,600 (6400*64)
    int row = i >> 6;
    int k = (i & 63) << 2;
    float4 v = make_float4(0.f, 0.f, 0.f, 0.f);
    if (row < MROWS) v = ((const float4*)g_X)[i];
    __nv_bfloat16* dst = g_A3 + (size_t)row * 768 + k;
    float xs[4] = {v.x, v.y, v.z, v.w};
    __align__(8) __nv_bfloat16 hi[4];
    __align__(8) __nv_bfloat16 lo[4];
    #pragma unroll
    for (int q = 0; q < 4; q++) {
        hi[q] = __float2bfloat16(xs[q]);
        lo[q] = __float2bfloat16(xs[q] - __bfloat162float(hi[q]));
    }
    *(uint2*)(dst)       = *(uint2*)hi;
    *(uint2*)(dst + 256) = *(uint2*)lo;
    *(uint2*)(dst + 512) = *(uint2*)hi;
}

// ---------------- mma.sync bf16 output GEMM (portable sm_80+ path) ----------------
// D[6400x32000] = A3[6400x768] @ B3[32000x768]^T + bout, fp32 accum.
// CTA tile 128x128, BK=32, cp.async double buffer, 8 warps (2x4), warp tile 64x32.
// SMEM rows padded to 80B (40 bf16): conflict-free ldmatrix (bank shift 20 words/row).

#define GLDA 40              // smem row stride in bf16 (80 bytes)
#define STAGE_B (128 * GLDA * 2)   // 10240 bytes per operand stage

__device__ __forceinline__ void cp16(uint32_t saddr, const void* gaddr) {
    asm volatile("cp.async.cg.shared.global [%0], [%1], 16;" :: "r"(saddr), "l"(gaddr));
}
__device__ __forceinline__ void ldsm_x4(uint32_t& r0, uint32_t& r1, uint32_t& r2, uint32_t& r3, uint32_t a) {
    asm volatile("ldmatrix.sync.aligned.m8n8.x4.shared.b16 {%0,%1,%2,%3}, [%4];"
                 : "=r"(r0), "=r"(r1), "=r"(r2), "=r"(r3) : "r"(a));
}
__device__ __forceinline__ void ldsm_x2(uint32_t& r0, uint32_t& r1, uint32_t a) {
    asm volatile("ldmatrix.sync.aligned.m8n8.x2.shared.b16 {%0,%1}, [%2];"
                 : "=r"(r0), "=r"(r1) : "r"(a));
}
__device__ __forceinline__ void mma16816(float* d, const uint32_t* a, const uint32_t* b) {
    asm volatile("mma.sync.aligned.m16n8k16.row.col.f32.bf16.bf16.f32 "
                 "{%0,%1,%2,%3}, {%4,%5,%6,%7}, {%8,%9}, {%0,%1,%2,%3};"
                 : "+f"(d[0]), "+f"(d[1]), "+f"(d[2]), "+f"(d[3])
                 : "r"(a[0]), "r"(a[1]), "r"(a[2]), "r"(a[3]), "r"(b[0]), "r"(b[1]));
}

__global__ void __launch_bounds__(256) gemm_mma(
    const float* __restrict__ bout, float* __restrict__ out)
{
    __shared__ __align__(16) __nv_bfloat16 As[2][128 * GLDA];
    __shared__ __align__(16) __nv_bfloat16 Bs[2][128 * GLDA];

    const int tid  = threadIdx.x;
    const int lane = tid & 31;
    const int wid  = tid >> 5;
    const int wm   = wid >> 2;          // 0..1 -> 64 rows each
    const int wn   = wid & 3;           // 0..3 -> 32 cols each
    const int ncol0 = blockIdx.x * 128;
    const int mrow0 = blockIdx.y * 128;

    const uint32_t asb = smem_u32(As);
    const uint32_t bsb = smem_u32(Bs);

    // gmem load mapping: row = tid>>1 (0..127), g2 = tid&1 -> 32B half-row
    const int lrow = tid >> 1, lg2 = tid & 1;
    const __nv_bfloat16* gA = g_A3 + (size_t)(mrow0 + lrow) * 768 + lg2 * 16;
    const __nv_bfloat16* gB = g_B3 + (size_t)(ncol0 + lrow) * 768 + lg2 * 16;
    const uint32_t sA = asb + lrow * 80 + lg2 * 32;
    const uint32_t sB = bsb + lrow * 80 + lg2 * 32;

    float acc[4][4][4] = {};

    // prologue: stage 0
    {
        cp16(sA,      gA);     cp16(sA + 16, gA + 8);
        cp16(sB,      gB);     cp16(sB + 16, gB + 8);
        asm volatile("cp.async.commit_group;");
    }

    for (int c = 0; c < 24; c++) {
        const int s = c & 1;
        asm volatile("cp.async.wait_group 0;");
        __syncthreads();
        if (c + 1 < 24) {
            const int s2 = (c + 1) & 1;
            const int ko = (c + 1) * 32;
            cp16(sA + s2 * STAGE_B,      gA + ko);
            cp16(sA + s2 * STAGE_B + 16, gA + ko + 8);
            cp16(sB + s2 * STAGE_B,      gB + ko);
            cp16(sB + s2 * STAGE_B + 16, gB + ko + 8);
            asm volatile("cp.async.commit_group;");
        }
        // compute stage s
        const uint32_t aBase = asb + s * STAGE_B;
        const uint32_t bBase = bsb + s * STAGE_B;
        #pragma unroll
        for (int s16 = 0; s16 < 2; s16++) {
            uint32_t a[4][4], b[4][2];
            #pragma unroll
            for (int mf = 0; mf < 4; mf++) {
                uint32_t addr = aBase + (wm * 64 + mf * 16 + (lane & 15)) * 80
                                       + (2 * s16 + (lane >> 4)) * 16;
                ldsm_x4(a[mf][0], a[mf][1], a[mf][2], a[mf][3], addr);
            }
            #pragma unroll
            for (int nf = 0; nf < 4; nf++) {
                uint32_t addr = bBase + (wn * 32 + nf * 8 + (lane & 7)) * 80
                                       + (2 * s16 + ((lane >> 3) & 1)) * 16;
                ldsm_x2(b[nf][0], b[nf][1], addr);
            }
            #pragma unroll
            for (int mf = 0; mf < 4; mf++)
                #pragma unroll
                for (int nf = 0; nf < 4; nf++)
                    mma16816(acc[mf][nf], a[mf], b[nf]);
        }
        __syncthreads();
    }

    // epilogue: bias + store
    #pragma unroll
    for (int mf = 0; mf < 4; mf++) {
        int r0 = mrow0 + wm * 64 + mf * 16 + (lane >> 2);
        int r1 = r0 + 8;
        #pragma unroll
        for (int nf = 0; nf < 4; nf++) {
            int gc = ncol0 + wn * 32 + nf * 8 + (lane & 3) * 2;
            float b0 = bout[gc], b1 = bout[gc + 1];
            if (r0 < MROWS) {
                float2 v = make_float2(acc[mf][nf][0] + b0, acc[mf][nf][1] + b1);
                *(float2*)&out[(size_t)r0 * VOC + gc] = v;
            }
            if (r1 < MROWS) {
                float2 v = make_float2(acc[mf][nf][2] + b0, acc[mf][nf][3] + b1);
                *(float2*)&out[(size_t)r1 * VOC + gc] = v;
            }
        }
    }
}

// ---------------- launch ----------------
extern "C" void kernel_launch(void* const* d_in, const int* in_sizes, int n_in,
                              void* d_out, int out_size)
{
    (void)in_sizes; (void)n_in; (void)out_size;
    const float* enc_key   = (const float*)d_in[0];
    const float* values    = (const float*)d_in[1];
    const int*   lens      = (const int*)  d_in[2];
    const int*   text      = (const int*)  d_in[3];
    const float* embedding = (const float*)d_in[4];
    const float* Wih1      = (const float*)d_in[5];
    const float* Whh1      = (const float*)d_in[6];
    const float* bih1      = (const float*)d_in[7];
    const float* bhh1      = (const float*)d_in[8];
    const float* Wih2      = (const float*)d_in[9];
    const float* Whh2      = (const float*)d_in[10];
    const float* bih2      = (const float*)d_in[11];
    const float* bhh2      = (const float*)d_in[12];
    const float* Wout      = (const float*)d_in[13];
    const float* bout      = (const float*)d_in[14];
    float* out = (float*)d_out;

    convB<<<8000, 256>>>(Wout);
    decoder_persist<<<NBLK, 256>>>(enc_key, values, lens, text, embedding,
                                   Wih1, Whh1, bih1, bhh1,
                                   Wih2, Whh2, bih2, bhh2, out);
    convA<<<1600, 256>>>();
    gemm_mma<<<dim3(250, 50), 256>>>(bout, out);
}

// round 6
// speedup vs baseline: 1.2266x; 1.0373x over previous
#include <cuda_runtime.h>
#include <cuda_bf16.h>
#include <cstdint>

// ---------------- problem constants ----------------
#define NB    64      // batch
#define TD    99      // decode steps (T_DEC-1)
#define TENC  512
#define HD    512
#define KSZ   128
#define VSZ   128
#define VOC   32000
#define NBLK  128     // persistent grid size (<= 148 SMs -> co-resident)

#define PRED_ELEMS (202752000LL)   // 64*99*32000
#define MROWS 6336                 // NB*TD
#define MPAD  6400                 // padded to 50*128

// ---------------- device scratch (static, no runtime alloc) ----------------
__device__ float g_h1 [HD * NB];     // [feature][batch]
__device__ float g_c1 [HD * NB];
__device__ float g_h2 [KSZ * NB];
__device__ float g_c2 [KSZ * NB];
__device__ float g_ctx[VSZ * NB];
__device__ float g_embt[HD * NB];           // gathered embeddings, [k][n]
__device__ float g_part1[4][4 * HD][NB];    // LSTM1 gate partials (ksplit=4)
__device__ float g_part2[8][4 * KSZ][NB];   // LSTM2 gate partials (ksplit=8)
__device__ float g_X[NB * TD * 256];        // [n*99+t][256] = concat(h2, ctx)

// bf16 split operands for output GEMM (K=768: [Ah|Al|Ah] x [Bh|Bh|Bl])
__device__ __nv_bfloat16 g_A3[(size_t)MPAD * 768];
__device__ __nv_bfloat16 g_B3[(size_t)VOC * 768];

// barrier state: cumulative arrivals + generation word (poll via plain loads)
__device__ unsigned g_cnt2;
__device__ volatile unsigned g_gen2;

__device__ __forceinline__ float sigf(float x) { return 1.0f / (1.0f + expf(-x)); }

__device__ __forceinline__ uint32_t smem_u32(const void* p) {
    uint32_t a;
    asm("{ .reg .u64 t; cvta.to.shared.u64 t, %1; cvt.u32.u64 %0, t; }" : "=r"(a) : "l"(p));
    return a;
}

// ---------------- fast software grid barrier ----------------
// Arrivals: single atomicAdd per block on a cumulative counter. Release: the
// 128th arriver bumps the generation word. Waiters poll with PLAIN volatile
// loads (no atomic-ALU contention on the release line). fence.acq_rel.gpu on
// both sides: publishes this block's writes / invalidates stale L1 lines
// (scope >= cluster => CCTL.IVALL on sm_103).
__device__ __forceinline__ void gridsync(unsigned &gen) {
    __syncthreads();
    if (threadIdx.x == 0) {
        asm volatile("fence.acq_rel.gpu;" ::: "memory");
        unsigned old = atomicAdd(&g_cnt2, 1u);
        if (old == gen * NBLK + (NBLK - 1)) {
            atomicExch((unsigned*)&g_gen2, gen + 1);
        } else {
            while (g_gen2 <= gen) { }
        }
        gen++;
        asm volatile("fence.acq_rel.gpu;" ::: "memory");
    }
    __syncthreads();
}

// ---------------- persistent recurrence kernel ----------------
__global__ void __launch_bounds__(256) decoder_persist(
    const float* __restrict__ enc_key, const float* __restrict__ values,
    const int* __restrict__ lens, const int* __restrict__ text,
    const float* __restrict__ emb,
    const float* __restrict__ Wih1, const float* __restrict__ Whh1,
    const float* __restrict__ bih1, const float* __restrict__ bhh1,
    const float* __restrict__ Wih2, const float* __restrict__ Whh2,
    const float* __restrict__ bih2, const float* __restrict__ bhh2,
    float* __restrict__ out)
{
    const int bx = blockIdx.x;
    const int tid = threadIdx.x;

    unsigned gen = 0;
    if (tid == 0) gen = g_gen2;     // snapshot before first arrival (replay-safe)

    __shared__ float xs1[32][64];
    __shared__ float ws1[32][68];
    __shared__ float xs2[16][64];
    __shared__ float ws2[16][68];
    __shared__ float h2s[KSZ];
    __shared__ float attn[TENC];
    __shared__ float redA[8];
    __shared__ float redB[8];
    __shared__ float cred[VSZ];

    // ---- init: blocks 0-63 zero state, blocks 64-127 gather embeddings t=0
    if (bx < 64) {
        #pragma unroll
        for (int j = 0; j < 2; j++) {
            int idx = (bx * 256 + tid) + j * 16384;
            g_h1[idx] = 0.f; g_c1[idx] = 0.f;
            if (idx < KSZ * NB) { g_h2[idx] = 0.f; g_c2[idx] = 0.f; g_ctx[idx] = 0.f; }
        }
    } else {
        int idx = (bx - 64) * 256 + tid;
        if (idx < 8192) {
            int k4 = idx & 127, n = idx >> 7;
            const float4 e = *(const float4*)&emb[(long long)text[n * 100 + 0] * 512 + k4 * 4];
            g_embt[(k4 * 4 + 0) * 64 + n] = e.x;
            g_embt[(k4 * 4 + 1) * 64 + n] = e.y;
            g_embt[(k4 * 4 + 2) * 64 + n] = e.z;
            g_embt[(k4 * 4 + 3) * 64 + n] = e.w;
        }
    }
    gridsync(gen);

    for (int t = 0; t < TD; t++) {
        // ================= phase 1a: LSTM1 gates partial GEMM =================
        {
            int jx = bx & 31, ksp = bx >> 5;
            int j0 = jx * 16;
            int kbase0 = ksp * 288;
            int nb = tid & 15, jg = tid >> 4;
            int n0 = nb * 4;
            float acc[4][4] = {};

            for (int kb = 0; kb < 288; kb += 32) {
                int kbase = kbase0 + kb;
                #pragma unroll
                for (int i = 0; i < 8; i++) {
                    int lin = tid + i * 256;
                    int kk = lin >> 6, nn = lin & 63;
                    int k = kbase + kk;
                    float v;
                    if (k < 512)       v = g_embt[k * 64 + nn];
                    else if (k < 640)  v = g_ctx[(k - 512) * NB + nn];
                    else               v = g_h1[(k - 640) * NB + nn];
                    xs1[kk][nn] = v;
                }
                #pragma unroll
                for (int i = 0; i < 2; i++) {
                    int lin = tid + i * 256;          // 0..511
                    int kk4 = lin & 7;
                    int c = lin >> 3;                 // jj*4+gate
                    int jj = c >> 2, gate = c & 3;
                    int grow = gate * 512 + j0 + jj;
                    int k = kbase + kk4 * 4;
                    float4 w = (k < 640) ? *(const float4*)&Wih1[grow * 640 + k]
                                         : *(const float4*)&Whh1[grow * 512 + (k - 640)];
                    ws1[kk4 * 4 + 0][c] = w.x; ws1[kk4 * 4 + 1][c] = w.y;
                    ws1[kk4 * 4 + 2][c] = w.z; ws1[kk4 * 4 + 3][c] = w.w;
                }
                __syncthreads();
                #pragma unroll
                for (int kk = 0; kk < 32; kk++) {
                    float4 xv = *(const float4*)&xs1[kk][n0];
                    float4 wv = *(const float4*)&ws1[kk][jg * 4];
                    float w4[4] = {wv.x, wv.y, wv.z, wv.w};
                    float x4[4] = {xv.x, xv.y, xv.z, xv.w};
                    #pragma unroll
                    for (int g = 0; g < 4; g++)
                        #pragma unroll
                        for (int b = 0; b < 4; b++)
                            acc[g][b] += w4[g] * x4[b];
                }
                __syncthreads();
            }
            #pragma unroll
            for (int g = 0; g < 4; g++)
                *(float4*)&g_part1[ksp][g * 512 + j0 + jg][n0] =
                    make_float4(acc[g][0], acc[g][1], acc[g][2], acc[g][3]);
        }
        gridsync(gen);

        // ================= phase 1b: LSTM1 reduce + cell update =================
        {
            int idx = bx * 256 + tid;
            int n = idx & 63, u = idx >> 6;
            float gi = 0.f, gf = 0.f, gg = 0.f, go = 0.f;
            #pragma unroll
            for (int s = 0; s < 4; s++) {
                gi += g_part1[s][u][n];
                gf += g_part1[s][u + 512][n];
                gg += g_part1[s][u + 1024][n];
                go += g_part1[s][u + 1536][n];
            }
            gi += bih1[u] + bhh1[u];
            gf += bih1[u + 512] + bhh1[u + 512];
            gg += bih1[u + 1024] + bhh1[u + 1024];
            go += bih1[u + 1536] + bhh1[u + 1536];
            float c = g_c1[u * NB + n];
            float cn = sigf(gf) * c + sigf(gi) * tanhf(gg);
            float hn = sigf(go) * tanhf(cn);
            g_c1[u * NB + n] = cn;
            g_h1[u * NB + n] = hn;
        }
        gridsync(gen);

        // ================= phase 2a: LSTM2 gates partial GEMM =================
        if (bx < 64) {
            int jx = bx & 7, ksp = bx >> 3;
            int j0 = jx * 16;
            int kbase0 = ksp * 80;
            int nb = tid & 15, jg = tid >> 4;
            int n0 = nb * 4;
            float acc[4][4] = {};

            for (int kb = 0; kb < 80; kb += 16) {
                int kbase = kbase0 + kb;
                #pragma unroll
                for (int i = 0; i < 4; i++) {
                    int lin = tid + i * 256;
                    int kk = lin >> 6, nn = lin & 63;
                    int k = kbase + kk;
                    xs2[kk][nn] = (k < 512) ? g_h1[k * NB + nn]
                                            : g_h2[(k - 512) * NB + nn];
                }
                {
                    int kk4 = tid & 3;
                    int c = tid >> 2;                  // 0..63
                    int jj = c >> 2, gate = c & 3;
                    int grow = gate * 128 + j0 + jj;
                    int k = kbase + kk4 * 4;
                    float4 w = (k < 512) ? *(const float4*)&Wih2[grow * 512 + k]
                                         : *(const float4*)&Whh2[grow * 128 + (k - 512)];
                    ws2[kk4 * 4 + 0][c] = w.x; ws2[kk4 * 4 + 1][c] = w.y;
                    ws2[kk4 * 4 + 2][c] = w.z; ws2[kk4 * 4 + 3][c] = w.w;
                }
                __syncthreads();
                #pragma unroll
                for (int kk = 0; kk < 16; kk++) {
                    float4 xv = *(const float4*)&xs2[kk][n0];
                    float4 wv = *(const float4*)&ws2[kk][jg * 4];
                    float w4[4] = {wv.x, wv.y, wv.z, wv.w};
                    float x4[4] = {xv.x, xv.y, xv.z, xv.w};
                    #pragma unroll
                    for (int g = 0; g < 4; g++)
                        #pragma unroll
                        for (int b = 0; b < 4; b++)
                            acc[g][b] += w4[g] * x4[b];
                }
                __syncthreads();
            }
            #pragma unroll
            for (int g = 0; g < 4; g++)
                *(float4*)&g_part2[ksp][g * 128 + j0 + jg][n0] =
                    make_float4(acc[g][0], acc[g][1], acc[g][2], acc[g][3]);
        }
        gridsync(gen);

        // ========== phase 3: LSTM2 cell + attention + context (blocks 0-63) ==========
        if (bx < 64) {
            int n = bx;

            if (tid < KSZ) {
                int u = tid;
                float gi = 0.f, gf = 0.f, gg = 0.f, go = 0.f;
                #pragma unroll
                for (int s = 0; s < 8; s++) {
                    gi += g_part2[s][u][n];
                    gf += g_part2[s][u + 128][n];
                    gg += g_part2[s][u + 256][n];
                    go += g_part2[s][u + 384][n];
                }
                gi += bih2[u] + bhh2[u];
                gf += bih2[u + 128] + bhh2[u + 128];
                gg += bih2[u + 256] + bhh2[u + 256];
                go += bih2[u + 384] + bhh2[u + 384];
                float c = g_c2[u * NB + n];
                float cn = sigf(gf) * c + sigf(gi) * tanhf(gg);
                float hn = sigf(go) * tanhf(cn);
                g_c2[u * NB + n] = cn;
                g_h2[u * NB + n] = hn;
                h2s[u] = hn;
                g_X[((long long)n * TD + t) * 256 + u] = hn;
            }
            __syncthreads();

            int len = lens[n];

            float e[2];
            #pragma unroll
            for (int q = 0; q < 2; q++) {
                int tau = tid + q * 256;
                float s = -1e30f;
                if (tau < len) {
                    s = 0.f;
                    const float4* ek = (const float4*)(enc_key + ((long long)n * TENC + tau) * KSZ);
                    const float4* hq = (const float4*)h2s;
                    #pragma unroll 8
                    for (int d = 0; d < 32; d++) {
                        float4 kv = ek[d]; float4 hv = hq[d];
                        s += kv.x * hv.x + kv.y * hv.y + kv.z * hv.z + kv.w * hv.w;
                    }
                }
                e[q] = s;
            }

            float m = fmaxf(e[0], e[1]);
            #pragma unroll
            for (int o = 16; o; o >>= 1) m = fmaxf(m, __shfl_xor_sync(0xffffffffu, m, o));
            if ((tid & 31) == 0) redA[tid >> 5] = m;
            __syncthreads();
            m = redA[0];
            #pragma unroll
            for (int w = 1; w < 8; w++) m = fmaxf(m, redA[w]);

            float p0 = (tid       < len) ? expf(e[0] - m) : 0.f;
            float p1 = (tid + 256 < len) ? expf(e[1] - m) : 0.f;
            float ssum = p0 + p1;
            #pragma unroll
            for (int o = 16; o; o >>= 1) ssum += __shfl_xor_sync(0xffffffffu, ssum, o);
            if ((tid & 31) == 0) redB[tid >> 5] = ssum;
            __syncthreads();
            float tot = redB[0];
            #pragma unroll
            for (int w = 1; w < 8; w++) tot += redB[w];
            float inv = 1.0f / tot;
            p0 *= inv; p1 *= inv;
            attn[tid] = p0;
            attn[tid + 256] = p1;
            long long ob = PRED_ELEMS + ((long long)n * TD + t) * TENC;
            out[ob + tid] = p0;
            out[ob + tid + 256] = p1;
            __syncthreads();

            int v = tid & 127, half = tid >> 7;
            float s4 = 0.f;
            const float* vp = values + (long long)n * TENC * VSZ + v;
            int tb = half * 256;
            #pragma unroll 8
            for (int tau = tb; tau < tb + 256; tau++)
                s4 += attn[tau] * vp[(long long)tau * VSZ];
            if (half == 1) cred[v] = s4;
            __syncthreads();
            if (half == 0) {
                float cv = s4 + cred[v];
                g_ctx[v * NB + n] = cv;
                g_X[((long long)n * TD + t) * 256 + 128 + v] = cv;
            }
        } else if (t + 1 < TD) {
            // blocks 64-127: gather embeddings for step t+1 (free overlap)
            int idx = (bx - 64) * 256 + tid;
            if (idx < 8192) {
                int k4 = idx & 127, n = idx >> 7;
                const float4 e = *(const float4*)&emb[(long long)text[n * 100 + (t + 1)] * 512 + k4 * 4];
                g_embt[(k4 * 4 + 0) * 64 + n] = e.x;
                g_embt[(k4 * 4 + 1) * 64 + n] = e.y;
                g_embt[(k4 * 4 + 2) * 64 + n] = e.z;
                g_embt[(k4 * 4 + 3) * 64 + n] = e.w;
            }
        }
        gridsync(gen);
    }
}

// ---------------- bf16 split conversion kernels ----------------
__global__ void __launch_bounds__(256) convB(const float* __restrict__ W) {
    int i = blockIdx.x * 256 + threadIdx.x;          // < 2,048,000 (32000*64)
    float4 v = ((const float4*)W)[i];
    int row = i >> 6;
    int k = (i & 63) << 2;
    __nv_bfloat16* dst = g_B3 + (size_t)row * 768 + k;
    float xs[4] = {v.x, v.y, v.z, v.w};
    __align__(8) __nv_bfloat16 hi[4];
    __align__(8) __nv_bfloat16 lo[4];
    #pragma unroll
    for (int q = 0; q < 4; q++) {
        hi[q] = __float2bfloat16(xs[q]);
        lo[q] = __float2bfloat16(xs[q] - __bfloat162float(hi[q]));
    }
    *(uint2*)(dst)       = *(uint2*)hi;
    *(uint2*)(dst + 256) = *(uint2*)hi;
    *(uint2*)(dst + 512) = *(uint2*)lo;
}

__global__ void __launch_bounds__(256) convA() {
    int i = blockIdx.x * 256 + threadIdx.x;          // < 409,600 (6400*64)
    int row = i >> 6;
    int k = (i & 63) << 2;
    float4 v = make_float4(0.f, 0.f, 0.f, 0.f);
    if (row < MROWS) v = ((const float4*)g_X)[i];
    __nv_bfloat16* dst = g_A3 + (size_t)row * 768 + k;
    float xs[4] = {v.x, v.y, v.z, v.w};
    __align__(8) __nv_bfloat16 hi[4];
    __align__(8) __nv_bfloat16 lo[4];
    #pragma unroll
    for (int q = 0; q < 4; q++) {
        hi[q] = __float2bfloat16(xs[q]);
        lo[q] = __float2bfloat16(xs[q] - __bfloat162float(hi[q]));
    }
    *(uint2*)(dst)       = *(uint2*)hi;
    *(uint2*)(dst + 256) = *(uint2*)lo;
    *(uint2*)(dst + 512) = *(uint2*)hi;
}

// ---------------- mma.sync bf16 output GEMM (3-stage cp.async pipeline) ----------------
// D[6400x32000] = A3[6400x768] @ B3[32000x768]^T + bout, fp32 accum.
// CTA tile 128x128, BK=32, 8 warps (2x4), warp tile 64x32, 80B-padded smem rows.

#define GLDA 40                        // smem row stride in bf16 (80 bytes)
#define STAGE_B (128 * GLDA * 2)       // 10240 bytes per operand per stage
#define NSTG 3
#define GDSM (NSTG * 2 * STAGE_B)      // 61440 bytes

__device__ __forceinline__ void cp16(uint32_t saddr, const void* gaddr) {
    asm volatile("cp.async.cg.shared.global [%0], [%1], 16;" :: "r"(saddr), "l"(gaddr));
}
__device__ __forceinline__ void ldsm_x4(uint32_t& r0, uint32_t& r1, uint32_t& r2, uint32_t& r3, uint32_t a) {
    asm volatile("ldmatrix.sync.aligned.m8n8.x4.shared.b16 {%0,%1,%2,%3}, [%4];"
                 : "=r"(r0), "=r"(r1), "=r"(r2), "=r"(r3) : "r"(a));
}
__device__ __forceinline__ void ldsm_x2(uint32_t& r0, uint32_t& r1, uint32_t a) {
    asm volatile("ldmatrix.sync.aligned.m8n8.x2.shared.b16 {%0,%1}, [%2];"
                 : "=r"(r0), "=r"(r1) : "r"(a));
}
__device__ __forceinline__ void mma16816(float* d, const uint32_t* a, const uint32_t* b) {
    asm volatile("mma.sync.aligned.m16n8k16.row.col.f32.bf16.bf16.f32 "
                 "{%0,%1,%2,%3}, {%4,%5,%6,%7}, {%8,%9}, {%0,%1,%2,%3};"
                 : "+f"(d[0]), "+f"(d[1]), "+f"(d[2]), "+f"(d[3])
                 : "r"(a[0]), "r"(a[1]), "r"(a[2]), "r"(a[3]), "r"(b[0]), "r"(b[1]));
}

__global__ void __launch_bounds__(256) gemm_mma(
    const float* __restrict__ bout, float* __restrict__ out)
{
    extern __shared__ __align__(16) char dsm[];

    const int tid  = threadIdx.x;
    const int lane = tid & 31;
    const int wid  = tid >> 5;
    const int wm   = wid >> 2;          // 0..1 -> 64 rows each
    const int wn   = wid & 3;           // 0..3 -> 32 cols each
    const int ncol0 = blockIdx.x * 128;
    const int mrow0 = blockIdx.y * 128;

    const uint32_t smb = smem_u32(dsm); // stage s: A at smb + s*2*STAGE_B, B at +STAGE_B

    const int lrow = tid >> 1, lg2 = tid & 1;
    const __nv_bfloat16* gA = g_A3 + (size_t)(mrow0 + lrow) * 768 + lg2 * 16;
    const __nv_bfloat16* gB = g_B3 + (size_t)(ncol0 + lrow) * 768 + lg2 * 16;
    const uint32_t sAo = lrow * 80 + lg2 * 32;

    float acc[4][4][4] = {};

    // prologue: stages 0,1
    #pragma unroll
    for (int p = 0; p < 2; p++) {
        uint32_t base = smb + p * 2 * STAGE_B;
        cp16(base + sAo,      gA + p * 32);
        cp16(base + sAo + 16, gA + p * 32 + 8);
        cp16(base + STAGE_B + sAo,      gB + p * 32);
        cp16(base + STAGE_B + sAo + 16, gB + p * 32 + 8);
        asm volatile("cp.async.commit_group;");
    }

    for (int c = 0; c < 24; c++) {
        if (c < 23) asm volatile("cp.async.wait_group 1;");
        else        asm volatile("cp.async.wait_group 0;");
        __syncthreads();
        if (c + 2 < 24) {
            const int s2 = (c + 2) % NSTG;
            const int ko = (c + 2) * 32;
            uint32_t base = smb + s2 * 2 * STAGE_B;
            cp16(base + sAo,      gA + ko);
            cp16(base + sAo + 16, gA + ko + 8);
            cp16(base + STAGE_B + sAo,      gB + ko);
            cp16(base + STAGE_B + sAo + 16, gB + ko + 8);
            asm volatile("cp.async.commit_group;");
        }
        const int s = c % NSTG;
        const uint32_t aBase = smb + s * 2 * STAGE_B;
        const uint32_t bBase = aBase + STAGE_B;
        #pragma unroll
        for (int s16 = 0; s16 < 2; s16++) {
            uint32_t a[4][4], b[4][2];
            #pragma unroll
            for (int mf = 0; mf < 4; mf++) {
                uint32_t addr = aBase + (wm * 64 + mf * 16 + (lane & 15)) * 80
                                       + (2 * s16 + (lane >> 4)) * 16;
                ldsm_x4(a[mf][0], a[mf][1], a[mf][2], a[mf][3], addr);
            }
            #pragma unroll
            for (int nf = 0; nf < 4; nf++) {
                uint32_t addr = bBase + (wn * 32 + nf * 8 + (lane & 7)) * 80
                                       + (2 * s16 + ((lane >> 3) & 1)) * 16;
                ldsm_x2(b[nf][0], b[nf][1], addr);
            }
            #pragma unroll
            for (int mf = 0; mf < 4; mf++)
                #pragma unroll
                for (int nf = 0; nf < 4; nf++)
                    mma16816(acc[mf][nf], a[mf], b[nf]);
        }
        __syncthreads();
    }

    // epilogue: bias + store
    #pragma unroll
    for (int mf = 0; mf < 4; mf++) {
        int r0 = mrow0 + wm * 64 + mf * 16 + (lane >> 2);
        int r1 = r0 + 8;
        #pragma unroll
        for (int nf = 0; nf < 4; nf++) {
            int gc = ncol0 + wn * 32 + nf * 8 + (lane & 3) * 2;
            float b0 = bout[gc], b1 = bout[gc + 1];
            if (r0 < MROWS) {
                float2 v = make_float2(acc[mf][nf][0] + b0, acc[mf][nf][1] + b1);
                *(float2*)&out[(size_t)r0 * VOC + gc] = v;
            }
            if (r1 < MROWS) {
                float2 v = make_float2(acc[mf][nf][2] + b0, acc[mf][nf][3] + b1);
                *(float2*)&out[(size_t)r1 * VOC + gc] = v;
            }
        }
    }
}

// ---------------- launch ----------------
extern "C" void kernel_launch(void* const* d_in, const int* in_sizes, int n_in,
                              void* d_out, int out_size)
{
    (void)in_sizes; (void)n_in; (void)out_size;
    const float* enc_key   = (const float*)d_in[0];
    const float* values    = (const float*)d_in[1];
    const int*   lens      = (const int*)  d_in[2];
    const int*   text      = (const int*)  d_in[3];
    const float* embedding = (const float*)d_in[4];
    const float* Wih1      = (const float*)d_in[5];
    const float* Whh1      = (const float*)d_in[6];
    const float* bih1      = (const float*)d_in[7];
    const float* bhh1      = (const float*)d_in[8];
    const float* Wih2      = (const float*)d_in[9];
    const float* Whh2      = (const float*)d_in[10];
    const float* bih2      = (const float*)d_in[11];
    const float* bhh2      = (const float*)d_in[12];
    const float* Wout      = (const float*)d_in[13];
    const float* bout      = (const float*)d_in[14];
    float* out = (float*)d_out;

    cudaFuncSetAttribute(gemm_mma, cudaFuncAttributeMaxDynamicSharedMemorySize, GDSM);

    convB<<<8000, 256>>>(Wout);
    decoder_persist<<<NBLK, 256>>>(enc_key, values, lens, text, embedding,
                                   Wih1, Whh1, bih1, bhh1,
                                   Wih2, Whh2, bih2, bhh2, out);
    convA<<<1600, 256>>>();
    gemm_mma<<<dim3(250, 50), 256, GDSM>>>(bout, out);
}

// round 7
// speedup vs baseline: 1.3237x; 1.0792x over previous
#include <cuda_runtime.h>
#include <cuda_bf16.h>
#include <cstdint>

// ---------------- problem constants ----------------
#define NB    64
#define TD    99
#define TENC  512
#define HD    512
#define KSZ   128
#define VSZ   128
#define VOC   32000
#define NBLK  128

#define PRED_ELEMS (202752000LL)
#define MROWS 6336
#define MPAD  6400

// ---------------- device scratch ----------------
__device__ float g_h1x[2][HD * NB];   // double-buffered, [feature][batch]
__device__ float g_c1 [HD * NB];
__device__ float g_h2x[2][KSZ * NB];
__device__ float g_c2 [KSZ * NB];
__device__ float g_ctx[VSZ * NB];
__device__ float g_embt[HD * NB];
__device__ float g_X[NB * TD * 256];

__device__ __nv_bfloat16 g_A3[(size_t)MPAD * 768];
__device__ __nv_bfloat16 g_B3[(size_t)VOC * 768];

// tree barrier state (monotonic, replay-safe)
__device__ unsigned g_grpc[16 * 32];   // 16 group counters, 128B apart
__device__ unsigned g_root;
__device__ volatile unsigned g_genw;

__device__ __forceinline__ float sigf(float x) { return 1.0f / (1.0f + expf(-x)); }

__device__ __forceinline__ uint32_t smem_u32(const void* p) {
    uint32_t a;
    asm("{ .reg .u64 t; cvta.to.shared.u64 t, %1; cvt.u32.u64 %0, t; }" : "=r"(a) : "l"(p));
    return a;
}
__device__ __forceinline__ void cpa16(uint32_t s, const void* g) {
    asm volatile("cp.async.cg.shared.global [%0], [%1], 16;" :: "r"(s), "l"(g));
}

// ---------------- tree grid barrier ----------------
__device__ __forceinline__ void gridsync(unsigned &gen, int bx) {
    __syncthreads();
    if (threadIdx.x == 0) {
        asm volatile("fence.acq_rel.gpu;" ::: "memory");
        unsigned old = atomicAdd(&g_grpc[(bx >> 3) * 32], 1u);
        if (old == gen * 8u + 7u) {
            unsigned rt = atomicAdd(&g_root, 1u);
            if (rt == gen * 16u + 15u) atomicExch((unsigned*)&g_genw, gen + 1u);
        }
        while (g_genw == gen) { }
        gen++;
        asm volatile("fence.acq_rel.gpu;" ::: "memory");
    }
    __syncthreads();
}

// ---------------- persistent recurrence kernel ----------------
__global__ void __launch_bounds__(256) decoder_persist(
    const float* __restrict__ enc_key, const float* __restrict__ values,
    const int* __restrict__ lens, const int* __restrict__ text,
    const float* __restrict__ emb,
    const float* __restrict__ Wih1, const float* __restrict__ Whh1,
    const float* __restrict__ bih1, const float* __restrict__ bhh1,
    const float* __restrict__ Wih2, const float* __restrict__ Whh2,
    const float* __restrict__ bih2, const float* __restrict__ bhh2,
    float* __restrict__ out)
{
    const int bx = blockIdx.x;
    const int tid = threadIdx.x;

    __shared__ __align__(16) char sm[45824];
    float* xs = (float*)sm;                 // [2][64*64]  (16 KB x2)
    float* ws = (float*)(sm + 32768);       // [2][16*68]
    float* sg = (float*)(sm + 41472);       // [16*68]
    // phase-C aliases (xs region, valid after gridsync)
    float* attn = (float*)sm;               // [512]
    float* h2s  = (float*)(sm + 2048);      // [128]
    float* redA = (float*)(sm + 2560);      // [8]
    float* redB = (float*)(sm + 2592);      // [8]
    float* cred = (float*)(sm + 2624);      // [128]

    const uint32_t xsB = smem_u32(xs);
    const uint32_t wsBy = smem_u32(ws);

    unsigned gen = 0;
    if (tid == 0) gen = g_genw;     // snapshot (replay-safe)

    // ----- phase-A static roles -----
    const int rA = tid >> 4;                 // 0..15 (compute & load row)
    const int n0 = (tid & 15) * 4;
    const int jA = rA & 3, gA = rA >> 2;
    const float* wihA = Wih1 + (size_t)(gA * 512 + bx * 4 + jA) * 640;
    const float* whhA = Whh1 + (size_t)(gA * 512 + bx * 4 + jA) * 512;
    const int jcA = tid >> 6, ncA = tid & 63;     // cell role
    const int ucA = bx * 4 + jcA;
    const float bI1 = bih1[ucA]        + bhh1[ucA];
    const float bF1 = bih1[512 + ucA]  + bhh1[512 + ucA];
    const float bG1 = bih1[1024 + ucA] + bhh1[1024 + ucA];
    const float bO1 = bih1[1536 + ucA] + bhh1[1536 + ucA];

    // ----- phase-B static roles -----
    const int rB = tid >> 5;                 // 0..7 compute row
    const int n0B = (tid & 31) * 2;
    const int wrB = tid >> 4;                // 0..7 load row (tid<128)
    const float* wihBL = Wih2 + (size_t)(((wrB >> 1) & 3) * 128 + bx * 2 + (wrB & 1)) * 512;
    const float* whhBL = Whh2 + (size_t)(((wrB >> 1) & 3) * 128 + bx * 2 + (wrB & 1)) * 128;
    const int ucB = bx * 2 + (tid >> 6);
    float bI2 = 0.f, bF2 = 0.f, bG2 = 0.f, bO2 = 0.f;
    if (bx < 64 && tid < 128) {
        bI2 = bih2[ucB]       + bhh2[ucB];
        bF2 = bih2[128 + ucB] + bhh2[128 + ucB];
        bG2 = bih2[256 + ucB] + bhh2[256 + ucB];
        bO2 = bih2[384 + ucB] + bhh2[384 + ucB];
    }

    // ---- init: zero state buffers + gather embeddings for t=0 ----
    if (bx < 64) {
        #pragma unroll
        for (int q = 0; q < 2; q++) {
            int idx = bx * 512 + q * 256 + tid;        // covers 32768
            g_h1x[0][idx] = 0.f; g_c1[idx] = 0.f;
            if (idx < KSZ * NB) { g_h2x[0][idx] = 0.f; g_c2[idx] = 0.f; g_ctx[idx] = 0.f; }
        }
    } else {
        int idx = (bx - 64) * 256 + tid;
        if (idx < 8192) {
            int k4 = idx & 127, nn = idx >> 7;
            const float4 e = *(const float4*)&emb[(long long)text[nn * 100 + 0] * 512 + k4 * 4];
            g_embt[(k4 * 4 + 0) * 64 + nn] = e.x;
            g_embt[(k4 * 4 + 1) * 64 + nn] = e.y;
            g_embt[(k4 * 4 + 2) * 64 + nn] = e.z;
            g_embt[(k4 * 4 + 3) * 64 + nn] = e.w;
        }
    }
    gridsync(gen, bx);

    for (int t = 0; t < TD; t++) {
        const int hb = t & 1;
        const float* h1r = g_h1x[hb];
        float* h1w = g_h1x[hb ^ 1];
        const float* h2r = g_h2x[hb];
        float* h2w = g_h2x[hb ^ 1];

        // =============== phase A: LSTM1 full-K GEMM + cell ===============
        {
            float a0 = 0.f, a1 = 0.f, a2 = 0.f, a3 = 0.f;

            // chunk issue: 18 chunks of K=64
            auto issueA = [&](int c, int b) {
                const float* wsrc = (c < 10) ? (wihA + c * 64) : (whhA + (c - 10) * 64);
                cpa16(wsBy + (b * 1088 + rA * 68 + (tid & 15) * 4) * 4, wsrc + (tid & 15) * 4);
                const float* xb = (c < 8) ? (g_embt + c * 4096)
                                 : (c < 10) ? (g_ctx + (c - 8) * 4096)
                                            : (h1r + (c - 10) * 4096);
                #pragma unroll
                for (int i = 0; i < 4; i++) {
                    int lin = tid + i * 256;
                    int off = (lin >> 4) * 64 + (lin & 15) * 4;
                    cpa16(xsB + (b * 4096 + off) * 4, xb + off);
                }
                asm volatile("cp.async.commit_group;");
            };

            issueA(0, 0);
            for (int c = 0; c < 18; c++) {
                const int buf = c & 1;
                if (c + 1 < 18) {
                    issueA(c + 1, (c + 1) & 1);
                    asm volatile("cp.async.wait_group 1;");
                } else {
                    asm volatile("cp.async.wait_group 0;");
                }
                __syncthreads();
                const float* xb = xs + buf * 4096;
                const float* wb = ws + buf * 1088 + rA * 68;
                #pragma unroll
                for (int k4 = 0; k4 < 16; k4++) {
                    float4 w4 = *(const float4*)&wb[k4 * 4];
                    float wv[4] = {w4.x, w4.y, w4.z, w4.w};
                    #pragma unroll
                    for (int e = 0; e < 4; e++) {
                        float4 x4 = *(const float4*)&xb[(k4 * 4 + e) * 64 + n0];
                        a0 += wv[e] * x4.x; a1 += wv[e] * x4.y;
                        a2 += wv[e] * x4.z; a3 += wv[e] * x4.w;
                    }
                }
                __syncthreads();
            }
            *(float4*)&sg[rA * 68 + n0] = make_float4(a0, a1, a2, a3);
            __syncthreads();
            // cell update: thread = (unit jcA, batch ncA)
            {
                float gi = sg[(0 + jcA) * 68 + ncA] + bI1;
                float gf = sg[(4 + jcA) * 68 + ncA] + bF1;
                float gg = sg[(8 + jcA) * 68 + ncA] + bG1;
                float go = sg[(12 + jcA) * 68 + ncA] + bO1;
                int cell = ucA * 64 + ncA;
                float c0 = g_c1[cell];
                float cn = sigf(gf) * c0 + sigf(gi) * tanhf(gg);
                float hn = sigf(go) * tanhf(cn);
                g_c1[cell] = cn;
                h1w[cell] = hn;
            }
        }
        gridsync(gen, bx);

        // =============== phase B: LSTM2 full-K GEMM + cell | emb gather ===============
        if (bx < 64) {
            float b0 = 0.f, b1v = 0.f;

            auto issueB = [&](int c, int b) {
                if (tid < 128) {
                    const float* wsrc = (c < 8) ? (wihBL + c * 64) : (whhBL + (c - 8) * 64);
                    cpa16(wsBy + (b * 1088 + wrB * 68 + (tid & 15) * 4) * 4, wsrc + (tid & 15) * 4);
                }
                const float* xb = (c < 8) ? (h1w + c * 4096) : (h2r + (c - 8) * 4096);
                #pragma unroll
                for (int i = 0; i < 4; i++) {
                    int lin = tid + i * 256;
                    int off = (lin >> 4) * 64 + (lin & 15) * 4;
                    cpa16(xsB + (b * 4096 + off) * 4, xb + off);
                }
                asm volatile("cp.async.commit_group;");
            };

            issueB(0, 0);
            for (int c = 0; c < 10; c++) {
                const int buf = c & 1;
                if (c + 1 < 10) {
                    issueB(c + 1, (c + 1) & 1);
                    asm volatile("cp.async.wait_group 1;");
                } else {
                    asm volatile("cp.async.wait_group 0;");
                }
                __syncthreads();
                const float* xb = xs + buf * 4096;
                const float* wb = ws + buf * 1088 + rB * 68;
                #pragma unroll
                for (int k4 = 0; k4 < 16; k4++) {
                    float4 w4 = *(const float4*)&wb[k4 * 4];
                    float wv[4] = {w4.x, w4.y, w4.z, w4.w};
                    #pragma unroll
                    for (int e = 0; e < 4; e++) {
                        float2 x2 = *(const float2*)&xb[(k4 * 4 + e) * 64 + n0B];
                        b0 += wv[e] * x2.x; b1v += wv[e] * x2.y;
                    }
                }
                __syncthreads();
            }
            *(float2*)&sg[rB * 68 + n0B] = make_float2(b0, b1v);
            __syncthreads();
            if (tid < 128) {
                int jc2 = tid >> 6, nn = tid & 63;
                float gi = sg[(0 + jc2) * 68 + nn] + bI2;
                float gf = sg[(2 + jc2) * 68 + nn] + bF2;
                float gg = sg[(4 + jc2) * 68 + nn] + bG2;
                float go = sg[(6 + jc2) * 68 + nn] + bO2;
                int cell = ucB * 64 + nn;
                float c0 = g_c2[cell];
                float cn = sigf(gf) * c0 + sigf(gi) * tanhf(gg);
                float hn = sigf(go) * tanhf(cn);
                g_c2[cell] = cn;
                h2w[cell] = hn;
            }
        } else if (t + 1 < TD) {
            int idx = (bx - 64) * 256 + tid;
            if (idx < 8192) {
                int k4 = idx & 127, nn = idx >> 7;
                const float4 e = *(const float4*)&emb[(long long)text[nn * 100 + (t + 1)] * 512 + k4 * 4];
                g_embt[(k4 * 4 + 0) * 64 + nn] = e.x;
                g_embt[(k4 * 4 + 1) * 64 + nn] = e.y;
                g_embt[(k4 * 4 + 2) * 64 + nn] = e.z;
                g_embt[(k4 * 4 + 3) * 64 + nn] = e.w;
            }
        }
        gridsync(gen, bx);

        // =============== phase C: attention + context (blocks 0-63) ===============
        if (bx < 64) {
            const int n = bx;
            if (tid < 128) {
                float hv = h2w[tid * 64 + n];
                h2s[tid] = hv;
                g_X[((size_t)n * TD + t) * 256 + tid] = hv;
            }
            __syncthreads();

            int len = lens[n];
            float e0 = -1e30f, e1 = -1e30f;
            {
                const float4* hq = (const float4*)h2s;
                if (tid < len) {
                    float s = 0.f;
                    const float4* ek = (const float4*)(enc_key + ((size_t)n * TENC + tid) * KSZ);
                    #pragma unroll 8
                    for (int d = 0; d < 32; d++) {
                        float4 kv = ek[d]; float4 hv = hq[d];
                        s += kv.x * hv.x + kv.y * hv.y + kv.z * hv.z + kv.w * hv.w;
                    }
                    e0 = s;
                }
                if (tid + 256 < len) {
                    float s = 0.f;
                    const float4* ek = (const float4*)(enc_key + ((size_t)n * TENC + tid + 256) * KSZ);
                    #pragma unroll 8
                    for (int d = 0; d < 32; d++) {
                        float4 kv = ek[d]; float4 hv = hq[d];
                        s += kv.x * hv.x + kv.y * hv.y + kv.z * hv.z + kv.w * hv.w;
                    }
                    e1 = s;
                }
            }

            float m = fmaxf(e0, e1);
            #pragma unroll
            for (int o = 16; o; o >>= 1) m = fmaxf(m, __shfl_xor_sync(0xffffffffu, m, o));
            if ((tid & 31) == 0) redA[tid >> 5] = m;
            __syncthreads();
            m = redA[0];
            #pragma unroll
            for (int w = 1; w < 8; w++) m = fmaxf(m, redA[w]);

            float p0 = (tid       < len) ? expf(e0 - m) : 0.f;
            float p1 = (tid + 256 < len) ? expf(e1 - m) : 0.f;
            float ssum = p0 + p1;
            #pragma unroll
            for (int o = 16; o; o >>= 1) ssum += __shfl_xor_sync(0xffffffffu, ssum, o);
            if ((tid & 31) == 0) redB[tid >> 5] = ssum;
            __syncthreads();
            float tot = redB[0];
            #pragma unroll
            for (int w = 1; w < 8; w++) tot += redB[w];
            float inv = 1.0f / tot;
            p0 *= inv; p1 *= inv;
            attn[tid] = p0;
            attn[tid + 256] = p1;
            size_t ob = PRED_ELEMS + ((size_t)n * TD + t) * TENC;
            out[ob + tid] = p0;
            out[ob + tid + 256] = p1;
            __syncthreads();

            int v = tid & 127, half = tid >> 7;
            float s4 = 0.f;
            const float* vp = values + (size_t)n * TENC * VSZ + v;
            int tb = half * 256;
            #pragma unroll 8
            for (int tau = tb; tau < tb + 256; tau++)
                s4 += attn[tau] * vp[(size_t)tau * VSZ];
            if (half == 1) cred[v] = s4;
            __syncthreads();
            if (half == 0) {
                float cv = s4 + cred[v];
                g_ctx[v * 64 + n] = cv;
                g_X[((size_t)n * TD + t) * 256 + 128 + v] = cv;
            }
        }
        gridsync(gen, bx);
    }
}

// ---------------- bf16 split conversion kernels ----------------
__global__ void __launch_bounds__(256) convB(const float* __restrict__ W) {
    int i = blockIdx.x * 256 + threadIdx.x;
    float4 v = ((const float4*)W)[i];
    int row = i >> 6;
    int k = (i & 63) << 2;
    __nv_bfloat16* dst = g_B3 + (size_t)row * 768 + k;
    float xv[4] = {v.x, v.y, v.z, v.w};
    __align__(8) __nv_bfloat16 hi[4];
    __align__(8) __nv_bfloat16 lo[4];
    #pragma unroll
    for (int q = 0; q < 4; q++) {
        hi[q] = __float2bfloat16(xv[q]);
        lo[q] = __float2bfloat16(xv[q] - __bfloat162float(hi[q]));
    }
    *(uint2*)(dst)       = *(uint2*)hi;
    *(uint2*)(dst + 256) = *(uint2*)hi;
    *(uint2*)(dst + 512) = *(uint2*)lo;
}

__global__ void __launch_bounds__(256) convA() {
    int i = blockIdx.x * 256 + threadIdx.x;
    int row = i >> 6;
    int k = (i & 63) << 2;
    float4 v = make_float4(0.f, 0.f, 0.f, 0.f);
    if (row < MROWS) v = ((const float4*)g_X)[i];
    __nv_bfloat16* dst = g_A3 + (size_t)row * 768 + k;
    float xv[4] = {v.x, v.y, v.z, v.w};
    __align__(8) __nv_bfloat16 hi[4];
    __align__(8) __nv_bfloat16 lo[4];
    #pragma unroll
    for (int q = 0; q < 4; q++) {
        hi[q] = __float2bfloat16(xv[q]);
        lo[q] = __float2bfloat16(xv[q] - __bfloat162float(hi[q]));
    }
    *(uint2*)(dst)       = *(uint2*)hi;
    *(uint2*)(dst + 256) = *(uint2*)lo;
    *(uint2*)(dst + 512) = *(uint2*)hi;
}

// ---------------- mma.sync bf16 output GEMM (3-stage cp.async) ----------------
#define GLDA 40
#define STAGE_B (128 * GLDA * 2)
#define NSTG 3
#define GDSM (NSTG * 2 * STAGE_B)

__device__ __forceinline__ void ldsm_x4(uint32_t& r0, uint32_t& r1, uint32_t& r2, uint32_t& r3, uint32_t a) {
    asm volatile("ldmatrix.sync.aligned.m8n8.x4.shared.b16 {%0,%1,%2,%3}, [%4];"
                 : "=r"(r0), "=r"(r1), "=r"(r2), "=r"(r3) : "r"(a));
}
__device__ __forceinline__ void ldsm_x2(uint32_t& r0, uint32_t& r1, uint32_t a) {
    asm volatile("ldmatrix.sync.aligned.m8n8.x2.shared.b16 {%0,%1}, [%2];"
                 : "=r"(r0), "=r"(r1) : "r"(a));
}
__device__ __forceinline__ void mma16816(float* d, const uint32_t* a, const uint32_t* b) {
    asm volatile("mma.sync.aligned.m16n8k16.row.col.f32.bf16.bf16.f32 "
                 "{%0,%1,%2,%3}, {%4,%5,%6,%7}, {%8,%9}, {%0,%1,%2,%3};"
                 : "+f"(d[0]), "+f"(d[1]), "+f"(d[2]), "+f"(d[3])
                 : "r"(a[0]), "r"(a[1]), "r"(a[2]), "r"(a[3]), "r"(b[0]), "r"(b[1]));
}

__global__ void __launch_bounds__(256) gemm_mma(
    const float* __restrict__ bout, float* __restrict__ out)
{
    extern __shared__ __align__(16) char dsm[];

    const int tid  = threadIdx.x;
    const int lane = tid & 31;
    const int wid  = tid >> 5;
    const int wm   = wid >> 2;
    const int wn   = wid & 3;
    const int ncol0 = blockIdx.x * 128;
    const int mrow0 = blockIdx.y * 128;

    const uint32_t smb = smem_u32(dsm);

    const int lrow = tid >> 1, lg2 = tid & 1;
    const __nv_bfloat16* gA = g_A3 + (size_t)(mrow0 + lrow) * 768 + lg2 * 16;
    const __nv_bfloat16* gB = g_B3 + (size_t)(ncol0 + lrow) * 768 + lg2 * 16;
    const uint32_t sAo = lrow * 80 + lg2 * 32;

    float acc[4][4][4] = {};

    #pragma unroll
    for (int p = 0; p < 2; p++) {
        uint32_t base = smb + p * 2 * STAGE_B;
        cpa16(base + sAo,      gA + p * 32);
        cpa16(base + sAo + 16, gA + p * 32 + 8);
        cpa16(base + STAGE_B + sAo,      gB + p * 32);
        cpa16(base + STAGE_B + sAo + 16, gB + p * 32 + 8);
        asm volatile("cp.async.commit_group;");
    }

    for (int c = 0; c < 24; c++) {
        if (c < 23) asm volatile("cp.async.wait_group 1;");
        else        asm volatile("cp.async.wait_group 0;");
        __syncthreads();
        if (c + 2 < 24) {
            const int s2 = (c + 2) % NSTG;
            const int ko = (c + 2) * 32;
            uint32_t base = smb + s2 * 2 * STAGE_B;
            cpa16(base + sAo,      gA + ko);
            cpa16(base + sAo + 16, gA + ko + 8);
            cpa16(base + STAGE_B + sAo,      gB + ko);
            cpa16(base + STAGE_B + sAo + 16, gB + ko + 8);
            asm volatile("cp.async.commit_group;");
        }
        const int s = c % NSTG;
        const uint32_t aBase = smb + s * 2 * STAGE_B;
        const uint32_t bBase = aBase + STAGE_B;
        #pragma unroll
        for (int s16 = 0; s16 < 2; s16++) {
            uint32_t a[4][4], b[4][2];
            #pragma unroll
            for (int mf = 0; mf < 4; mf++) {
                uint32_t addr = aBase + (wm * 64 + mf * 16 + (lane & 15)) * 80
                                       + (2 * s16 + (lane >> 4)) * 16;
                ldsm_x4(a[mf][0], a[mf][1], a[mf][2], a[mf][3], addr);
            }
            #pragma unroll
            for (int nf = 0; nf < 4; nf++) {
                uint32_t addr = bBase + (wn * 32 + nf * 8 + (lane & 7)) * 80
                                       + (2 * s16 + ((lane >> 3) & 1)) * 16;
                ldsm_x2(b[nf][0], b[nf][1], addr);
            }
            #pragma unroll
            for (int mf = 0; mf < 4; mf++)
                #pragma unroll
                for (int nf = 0; nf < 4; nf++)
                    mma16816(acc[mf][nf], a[mf], b[nf]);
        }
        __syncthreads();
    }

    #pragma unroll
    for (int mf = 0; mf < 4; mf++) {
        int r0 = mrow0 + wm * 64 + mf * 16 + (lane >> 2);
        int r1 = r0 + 8;
        #pragma unroll
        for (int nf = 0; nf < 4; nf++) {
            int gc = ncol0 + wn * 32 + nf * 8 + (lane & 3) * 2;
            float b0 = bout[gc], b1 = bout[gc + 1];
            if (r0 < MROWS) {
                float2 v = make_float2(acc[mf][nf][0] + b0, acc[mf][nf][1] + b1);
                *(float2*)&out[(size_t)r0 * VOC + gc] = v;
            }
            if (r1 < MROWS) {
                float2 v = make_float2(acc[mf][nf][2] + b0, acc[mf][nf][3] + b1);
                *(float2*)&out[(size_t)r1 * VOC + gc] = v;
            }
        }
    }
}

// ---------------- launch ----------------
extern "C" void kernel_launch(void* const* d_in, const int* in_sizes, int n_in,
                              void* d_out, int out_size)
{
    (void)in_sizes; (void)n_in; (void)out_size;
    const float* enc_key   = (const float*)d_in[0];
    const float* values    = (const float*)d_in[1];
    const int*   lens      = (const int*)  d_in[2];
    const int*   text      = (const int*)  d_in[3];
    const float* embedding = (const float*)d_in[4];
    const float* Wih1      = (const float*)d_in[5];
    const float* Whh1      = (const float*)d_in[6];
    const float* bih1      = (const float*)d_in[7];
    const float* bhh1      = (const float*)d_in[8];
    const float* Wih2      = (const float*)d_in[9];
    const float* Whh2      = (const float*)d_in[10];
    const float* bih2      = (const float*)d_in[11];
    const float* bhh2      = (const float*)d_in[12];
    const float* Wout      = (const float*)d_in[13];
    const float* bout      = (const float*)d_in[14];
    float* out = (float*)d_out;

    cudaFuncSetAttribute(gemm_mma, cudaFuncAttributeMaxDynamicSharedMemorySize, GDSM);

    convB<<<8000, 256>>>(Wout);
    decoder_persist<<<NBLK, 256>>>(enc_key, values, lens, text, embedding,
                                   Wih1, Whh1, bih1, bhh1,
                                   Wih2, Whh2, bih2, bhh2, out);
    convA<<<1600, 256>>>();
    gemm_mma<<<dim3(250, 50), 256, GDSM>>>(bout, out);
}

// round 8
// speedup vs baseline: 1.4415x; 1.0891x over previous
#include <cuda_runtime.h>
#include <cuda_bf16.h>
#include <cstdint>

// ---------------- problem constants ----------------
#define NB    64
#define TD    99
#define TENC  512
#define HD    512
#define KSZ   128
#define VSZ   128
#define VOC   32000
#define NBLK  128

#define PRED_ELEMS (202752000LL)
#define MROWS 6336
#define MPAD  6400

// smem layout (persist kernel)
#define XBUF_B   17408            // one x buffer: 64 k rows x 272 B
#define WS_OFF   34816            // after 2 x buffers (also partials region)
#define WBUF_B   4416             // one w buffer: 16 rows x 276 B
#define SM_TOTAL 43648

// ---------------- device scratch ----------------
__device__ float g_h1x[2][HD * NB];   // double-buffered, [feature][batch]
__device__ float g_c1 [HD * NB];
__device__ float g_h2x[2][KSZ * NB];
__device__ float g_c2 [KSZ * NB];
__device__ float g_ctx[VSZ * NB];
__device__ float g_embt[HD * NB];
__device__ float g_X[NB * TD * 256];

__device__ __nv_bfloat16 g_A3[(size_t)MPAD * 768];
__device__ __nv_bfloat16 g_B3[(size_t)VOC * 768];

// tree barrier state (monotonic, replay-safe)
__device__ unsigned g_grpc[16 * 32];
__device__ unsigned g_root;
__device__ volatile unsigned g_genw;

__device__ __forceinline__ float sigf(float x) { return 1.0f / (1.0f + expf(-x)); }

__device__ __forceinline__ uint32_t smem_u32(const void* p) {
    uint32_t a;
    asm("{ .reg .u64 t; cvta.to.shared.u64 t, %1; cvt.u32.u64 %0, t; }" : "=r"(a) : "l"(p));
    return a;
}
__device__ __forceinline__ void cpa16(uint32_t s, const void* g) {
    asm volatile("cp.async.cg.shared.global [%0], [%1], 16;" :: "r"(s), "l"(g));
}

// ---------------- tree grid barrier ----------------
__device__ __forceinline__ void gridsync(unsigned &gen, int bx) {
    __syncthreads();
    if (threadIdx.x == 0) {
        asm volatile("fence.acq_rel.gpu;" ::: "memory");
        unsigned old = atomicAdd(&g_grpc[(bx >> 3) * 32], 1u);
        if (old == gen * 8u + 7u) {
            unsigned rt = atomicAdd(&g_root, 1u);
            if (rt == gen * 16u + 15u) atomicExch((unsigned*)&g_genw, gen + 1u);
        }
        while (g_genw == gen) { }
        gen++;
        asm volatile("fence.acq_rel.gpu;" ::: "memory");
    }
    __syncthreads();
}

// ---------------- persistent recurrence kernel ----------------
__global__ void __launch_bounds__(256) decoder_persist(
    const float* __restrict__ enc_key, const float* __restrict__ values,
    const int* __restrict__ lens, const int* __restrict__ text,
    const float* __restrict__ emb,
    const float* __restrict__ Wih1, const float* __restrict__ Whh1,
    const float* __restrict__ bih1, const float* __restrict__ bhh1,
    const float* __restrict__ Wih2, const float* __restrict__ Whh2,
    const float* __restrict__ bih2, const float* __restrict__ bhh2,
    float* __restrict__ out)
{
    const int bx = blockIdx.x;
    const int tid = threadIdx.x;

    __shared__ __align__(16) char sm[SM_TOTAL];
    const uint32_t smB = smem_u32(sm);

    // phase-C aliases (first 3 KB of xs region)
    float* attn = (float*)sm;               // [512]
    float* h2s  = (float*)(sm + 2048);      // [128]
    float* redA = (float*)(sm + 2560);      // [8]
    float* redB = (float*)(sm + 2592);      // [8]
    float* cred = (float*)(sm + 2624);      // [128]

    unsigned gen = 0;
    if (tid == 0) gen = g_genw;

    const int wp   = tid >> 5;      // warp id = k-split
    const int lane = tid & 31;
    const int rgA  = lane >> 3;     // gate 0..3
    const int bgA  = lane & 7;      // batch group (8 each)

    // weight loader roles (A: 16 rows, B: 8 rows)
    const int wr   = tid >> 4;      // 0..15
    const int wseg = tid & 15;
    const int grA  = (wr >> 2) * 512 + bx * 4 + (wr & 3);
    const float* wihRowA = Wih1 + (size_t)grA * 640;
    const float* whhRowA = Whh1 + (size_t)grA * 512;
    const int grB  = ((wr >> 1) & 3) * 128 + bx * 2 + (wr & 1);
    const float* wihRowB = Wih2 + (size_t)grB * 512;
    const float* whhRowB = Whh2 + (size_t)grB * 128;

    // cell roles + biases
    const int jcA = tid >> 6, ncA = tid & 63;
    const int ucA = bx * 4 + jcA;
    const float bI1 = bih1[ucA]        + bhh1[ucA];
    const float bF1 = bih1[512 + ucA]  + bhh1[512 + ucA];
    const float bG1 = bih1[1024 + ucA] + bhh1[1024 + ucA];
    const float bO1 = bih1[1536 + ucA] + bhh1[1536 + ucA];
    const int ucB = bx * 2 + (tid >> 6);
    float bI2 = 0.f, bF2 = 0.f, bG2 = 0.f, bO2 = 0.f;
    if (bx < 64 && tid < 128) {
        bI2 = bih2[ucB]       + bhh2[ucB];
        bF2 = bih2[128 + ucB] + bhh2[128 + ucB];
        bG2 = bih2[256 + ucB] + bhh2[256 + ucB];
        bO2 = bih2[384 + ucB] + bhh2[384 + ucB];
    }

    // ---- init ----
    if (bx < 64) {
        #pragma unroll
        for (int q = 0; q < 2; q++) {
            int idx = bx * 512 + q * 256 + tid;
            g_h1x[0][idx] = 0.f; g_c1[idx] = 0.f;
            if (idx < KSZ * NB) { g_h2x[0][idx] = 0.f; g_c2[idx] = 0.f; g_ctx[idx] = 0.f; }
        }
    } else {
        int idx = (bx - 64) * 256 + tid;
        if (idx < 8192) {
            int k4 = idx & 127, nn = idx >> 7;
            const float4 e = *(const float4*)&emb[(long long)text[nn * 100 + 0] * 512 + k4 * 4];
            g_embt[(k4 * 4 + 0) * 64 + nn] = e.x;
            g_embt[(k4 * 4 + 1) * 64 + nn] = e.y;
            g_embt[(k4 * 4 + 2) * 64 + nn] = e.z;
            g_embt[(k4 * 4 + 3) * 64 + nn] = e.w;
        }
    }
    gridsync(gen, bx);

    for (int t = 0; t < TD; t++) {
        const int hb = t & 1;
        const float* h1r = g_h1x[hb];
        float* h1w = g_h1x[hb ^ 1];
        const float* h2r = g_h2x[hb];
        float* h2w = g_h2x[hb ^ 1];

        // =============== phase A: LSTM1 (16 rows x 64 batch, K=1152) ===============
        {
            float a[4][8];
            #pragma unroll
            for (int j = 0; j < 4; j++)
                #pragma unroll
                for (int b = 0; b < 8; b++) a[j][b] = 0.f;

            // x chunk streamer
            auto ldxA = [&](int c) {
                const float* xsrc = (c < 8) ? (g_embt + c * 4096)
                                  : (c < 10) ? (g_ctx + (c - 8) * 4096)
                                             : (h1r + (c - 10) * 4096);
                uint32_t dst = smB + (uint32_t)(c & 1) * XBUF_B;
                #pragma unroll
                for (int i = 0; i < 4; i++) {
                    int lin = tid + i * 256;
                    int kl = lin >> 4, b4 = lin & 15;
                    cpa16(dst + kl * 272 + b4 * 16, xsrc + kl * 64 + b4 * 4);
                }
                asm volatile("cp.async.commit_group;");
            };
            auto ldwA = [&](int c) -> float4 {
                return (c < 10) ? *(const float4*)(wihRowA + c * 64 + wseg * 4)
                                : *(const float4*)(whhRowA + (c - 10) * 64 + wseg * 4);
            };
            auto stwA = [&](int c, float4 v) {
                float* d = (float*)(sm + WS_OFF + (c & 1) * WBUF_B) + wr * 69 + wseg * 4;
                d[0] = v.x; d[1] = v.y; d[2] = v.z; d[3] = v.w;
            };

            float4 wreg = ldwA(0);
            stwA(0, wreg);
            ldxA(0);
            wreg = ldwA(1);

            for (int c = 0; c < 18; c++) {
                asm volatile("cp.async.wait_group 0;");
                __syncthreads();
                if (c + 1 < 18) {
                    ldxA(c + 1);
                    stwA(c + 1, wreg);
                    if (c + 2 < 18) wreg = ldwA(c + 2);
                }
                const char* xb = sm + (c & 1) * XBUF_B;
                const float* wb = (const float*)(sm + WS_OFF + (c & 1) * WBUF_B);
                #pragma unroll
                for (int kk = 0; kk < 8; kk++) {
                    const int kl = wp * 8 + kk;
                    float w0 = wb[(rgA * 4 + 0) * 69 + kl];
                    float w1 = wb[(rgA * 4 + 1) * 69 + kl];
                    float w2 = wb[(rgA * 4 + 2) * 69 + kl];
                    float w3 = wb[(rgA * 4 + 3) * 69 + kl];
                    const char* xr = xb + kl * 272 + bgA * 32;
                    float4 x0 = *(const float4*)xr;
                    float4 x1 = *(const float4*)(xr + 16);
                    float xv[8] = {x0.x, x0.y, x0.z, x0.w, x1.x, x1.y, x1.z, x1.w};
                    #pragma unroll
                    for (int b = 0; b < 8; b++) {
                        a[0][b] += w0 * xv[b]; a[1][b] += w1 * xv[b];
                        a[2][b] += w2 * xv[b]; a[3][b] += w3 * xv[b];
                    }
                }
            }
            __syncthreads();
            // write warp partials into xs region: part[wp][row][batch], row stride 272B
            #pragma unroll
            for (int j = 0; j < 4; j++) {
                char* p = sm + wp * 4352 + (rgA * 4 + j) * 272 + bgA * 32;
                *(float4*)p        = make_float4(a[j][0], a[j][1], a[j][2], a[j][3]);
                *(float4*)(p + 16) = make_float4(a[j][4], a[j][5], a[j][6], a[j][7]);
            }
            __syncthreads();
            // reduce 8 partials -> red (ws region), row stride 272B
            {
                int row = tid >> 4, seg = tid & 15;
                char* base = sm + row * 272 + seg * 16;
                float4 s = *(float4*)base;
                #pragma unroll
                for (int w = 1; w < 8; w++) {
                    float4 v = *(float4*)(base + w * 4352);
                    s.x += v.x; s.y += v.y; s.z += v.z; s.w += v.w;
                }
                *(float4*)(sm + WS_OFF + row * 272 + seg * 16) = s;
            }
            __syncthreads();
            // cell update
            {
                const float* red = (const float*)(sm + WS_OFF);
                float gi = red[(0 * 4 + jcA) * 68 + ncA] + bI1;
                float gf = red[(1 * 4 + jcA) * 68 + ncA] + bF1;
                float gg = red[(2 * 4 + jcA) * 68 + ncA] + bG1;
                float go = red[(3 * 4 + jcA) * 68 + ncA] + bO1;
                int cell = ucA * 64 + ncA;
                float c0 = g_c1[cell];
                float cn = sigf(gf) * c0 + sigf(gi) * tanhf(gg);
                float hn = sigf(go) * tanhf(cn);
                g_c1[cell] = cn;
                h1w[cell] = hn;
            }
        }
        gridsync(gen, bx);

        // =============== phase B: LSTM2 (8 rows x 64 batch, K=640) | emb gather ===============
        if (bx < 64) {
            float a[2][8];
            #pragma unroll
            for (int j = 0; j < 2; j++)
                #pragma unroll
                for (int b = 0; b < 8; b++) a[j][b] = 0.f;

            auto ldxB = [&](int c) {
                const float* xsrc = (c < 8) ? (h1w + c * 4096) : (h2r + (c - 8) * 4096);
                uint32_t dst = smB + (uint32_t)(c & 1) * XBUF_B;
                #pragma unroll
                for (int i = 0; i < 4; i++) {
                    int lin = tid + i * 256;
                    int kl = lin >> 4, b4 = lin & 15;
                    cpa16(dst + kl * 272 + b4 * 16, xsrc + kl * 64 + b4 * 4);
                }
                asm volatile("cp.async.commit_group;");
            };
            auto ldwB = [&](int c) -> float4 {
                if (tid >= 128) return make_float4(0.f, 0.f, 0.f, 0.f);
                return (c < 8) ? *(const float4*)(wihRowB + c * 64 + wseg * 4)
                               : *(const float4*)(whhRowB + (c - 8) * 64 + wseg * 4);
            };
            auto stwB = [&](int c, float4 v) {
                if (tid < 128) {
                    float* d = (float*)(sm + WS_OFF + (c & 1) * WBUF_B) + wr * 69 + wseg * 4;
                    d[0] = v.x; d[1] = v.y; d[2] = v.z; d[3] = v.w;
                }
            };

            float4 wreg = ldwB(0);
            stwB(0, wreg);
            ldxB(0);
            wreg = ldwB(1);

            for (int c = 0; c < 10; c++) {
                asm volatile("cp.async.wait_group 0;");
                __syncthreads();
                if (c + 1 < 10) {
                    ldxB(c + 1);
                    stwB(c + 1, wreg);
                    if (c + 2 < 10) wreg = ldwB(c + 2);
                }
                const char* xb = sm + (c & 1) * XBUF_B;
                const float* wb = (const float*)(sm + WS_OFF + (c & 1) * WBUF_B);
                #pragma unroll
                for (int kk = 0; kk < 8; kk++) {
                    const int kl = wp * 8 + kk;
                    float w0 = wb[(rgA * 2 + 0) * 69 + kl];
                    float w1 = wb[(rgA * 2 + 1) * 69 + kl];
                    const char* xr = xb + kl * 272 + bgA * 32;
                    float4 x0 = *(const float4*)xr;
                    float4 x1 = *(const float4*)(xr + 16);
                    float xv[8] = {x0.x, x0.y, x0.z, x0.w, x1.x, x1.y, x1.z, x1.w};
                    #pragma unroll
                    for (int b = 0; b < 8; b++) {
                        a[0][b] += w0 * xv[b];
                        a[1][b] += w1 * xv[b];
                    }
                }
            }
            __syncthreads();
            #pragma unroll
            for (int j = 0; j < 2; j++) {
                char* p = sm + wp * 2176 + (rgA * 2 + j) * 272 + bgA * 32;
                *(float4*)p        = make_float4(a[j][0], a[j][1], a[j][2], a[j][3]);
                *(float4*)(p + 16) = make_float4(a[j][4], a[j][5], a[j][6], a[j][7]);
            }
            __syncthreads();
            if (tid < 128) {
                int row = tid >> 4, seg = tid & 15;
                char* base = sm + row * 272 + seg * 16;
                float4 s = *(float4*)base;
                #pragma unroll
                for (int w = 1; w < 8; w++) {
                    float4 v = *(float4*)(base + w * 2176);
                    s.x += v.x; s.y += v.y; s.z += v.z; s.w += v.w;
                }
                *(float4*)(sm + WS_OFF + row * 272 + seg * 16) = s;
            }
            __syncthreads();
            if (tid < 128) {
                const float* red = (const float*)(sm + WS_OFF);
                int jc2 = tid >> 6, nn = tid & 63;
                float gi = red[(0 * 2 + jc2) * 68 + nn] + bI2;
                float gf = red[(1 * 2 + jc2) * 68 + nn] + bF2;
                float gg = red[(2 * 2 + jc2) * 68 + nn] + bG2;
                float go = red[(3 * 2 + jc2) * 68 + nn] + bO2;
                int cell = ucB * 64 + nn;
                float c0 = g_c2[cell];
                float cn = sigf(gf) * c0 + sigf(gi) * tanhf(gg);
                float hn = sigf(go) * tanhf(cn);
                g_c2[cell] = cn;
                h2w[cell] = hn;
            }
        } else if (t + 1 < TD) {
            int idx = (bx - 64) * 256 + tid;
            if (idx < 8192) {
                int k4 = idx & 127, nn = idx >> 7;
                const float4 e = *(const float4*)&emb[(long long)text[nn * 100 + (t + 1)] * 512 + k4 * 4];
                g_embt[(k4 * 4 + 0) * 64 + nn] = e.x;
                g_embt[(k4 * 4 + 1) * 64 + nn] = e.y;
                g_embt[(k4 * 4 + 2) * 64 + nn] = e.z;
                g_embt[(k4 * 4 + 3) * 64 + nn] = e.w;
            }
        }
        gridsync(gen, bx);

        // =============== phase C: attention + context (blocks 0-63) ===============
        if (bx < 64) {
            const int n = bx;
            if (tid < 128) {
                float hv = h2w[tid * 64 + n];
                h2s[tid] = hv;
                g_X[((size_t)n * TD + t) * 256 + tid] = hv;
            }
            __syncthreads();

            int len = lens[n];
            float e0 = -1e30f, e1 = -1e30f;
            {
                const float4* hq = (const float4*)h2s;
                if (tid < len) {
                    float s = 0.f;
                    const float4* ek = (const float4*)(enc_key + ((size_t)n * TENC + tid) * KSZ);
                    #pragma unroll 8
                    for (int d = 0; d < 32; d++) {
                        float4 kv = ek[d]; float4 hv = hq[d];
                        s += kv.x * hv.x + kv.y * hv.y + kv.z * hv.z + kv.w * hv.w;
                    }
                    e0 = s;
                }
                if (tid + 256 < len) {
                    float s = 0.f;
                    const float4* ek = (const float4*)(enc_key + ((size_t)n * TENC + tid + 256) * KSZ);
                    #pragma unroll 8
                    for (int d = 0; d < 32; d++) {
                        float4 kv = ek[d]; float4 hv = hq[d];
                        s += kv.x * hv.x + kv.y * hv.y + kv.z * hv.z + kv.w * hv.w;
                    }
                    e1 = s;
                }
            }

            float m = fmaxf(e0, e1);
            #pragma unroll
            for (int o = 16; o; o >>= 1) m = fmaxf(m, __shfl_xor_sync(0xffffffffu, m, o));
            if ((tid & 31) == 0) redA[tid >> 5] = m;
            __syncthreads();
            m = redA[0];
            #pragma unroll
            for (int w = 1; w < 8; w++) m = fmaxf(m, redA[w]);

            float p0 = (tid       < len) ? expf(e0 - m) : 0.f;
            float p1 = (tid + 256 < len) ? expf(e1 - m) : 0.f;
            float ssum = p0 + p1;
            #pragma unroll
            for (int o = 16; o; o >>= 1) ssum += __shfl_xor_sync(0xffffffffu, ssum, o);
            if ((tid & 31) == 0) redB[tid >> 5] = ssum;
            __syncthreads();
            float tot = redB[0];
            #pragma unroll
            for (int w = 1; w < 8; w++) tot += redB[w];
            float inv = 1.0f / tot;
            p0 *= inv; p1 *= inv;
            attn[tid] = p0;
            attn[tid + 256] = p1;
            size_t ob = PRED_ELEMS + ((size_t)n * TD + t) * TENC;
            out[ob + tid] = p0;
            out[ob + tid + 256] = p1;
            __syncthreads();

            int v = tid & 127, half = tid >> 7;
            float s4 = 0.f;
            const float* vp = values + (size_t)n * TENC * VSZ + v;
            int tb = half * 256;
            #pragma unroll 8
            for (int tau = tb; tau < tb + 256; tau++)
                s4 += attn[tau] * vp[(size_t)tau * VSZ];
            if (half == 1) cred[v] = s4;
            __syncthreads();
            if (half == 0) {
                float cv = s4 + cred[v];
                g_ctx[v * 64 + n] = cv;
                g_X[((size_t)n * TD + t) * 256 + 128 + v] = cv;
            }
        }
        gridsync(gen, bx);
    }
}

// ---------------- bf16 split conversion kernels ----------------
__global__ void __launch_bounds__(256) convB(const float* __restrict__ W) {
    int i = blockIdx.x * 256 + threadIdx.x;
    float4 v = ((const float4*)W)[i];
    int row = i >> 6;
    int k = (i & 63) << 2;
    __nv_bfloat16* dst = g_B3 + (size_t)row * 768 + k;
    float xv[4] = {v.x, v.y, v.z, v.w};
    __align__(8) __nv_bfloat16 hi[4];
    __align__(8) __nv_bfloat16 lo[4];
    #pragma unroll
    for (int q = 0; q < 4; q++) {
        hi[q] = __float2bfloat16(xv[q]);
        lo[q] = __float2bfloat16(xv[q] - __bfloat162float(hi[q]));
    }
    *(uint2*)(dst)       = *(uint2*)hi;
    *(uint2*)(dst + 256) = *(uint2*)hi;
    *(uint2*)(dst + 512) = *(uint2*)lo;
}

__global__ void __launch_bounds__(256) convA() {
    int i = blockIdx.x * 256 + threadIdx.x;
    int row = i >> 6;
    int k = (i & 63) << 2;
    float4 v = make_float4(0.f, 0.f, 0.f, 0.f);
    if (row < MROWS) v = ((const float4*)g_X)[i];
    __nv_bfloat16* dst = g_A3 + (size_t)row * 768 + k;
    float xv[4] = {v.x, v.y, v.z, v.w};
    __align__(8) __nv_bfloat16 hi[4];
    __align__(8) __nv_bfloat16 lo[4];
    #pragma unroll
    for (int q = 0; q < 4; q++) {
        hi[q] = __float2bfloat16(xv[q]);
        lo[q] = __float2bfloat16(xv[q] - __bfloat162float(hi[q]));
    }
    *(uint2*)(dst)       = *(uint2*)hi;
    *(uint2*)(dst + 256) = *(uint2*)lo;
    *(uint2*)(dst + 512) = *(uint2*)hi;
}

// ---------------- mma.sync bf16 output GEMM (3-stage cp.async) ----------------
#define GLDA 40
#define STAGE_B (128 * GLDA * 2)
#define NSTG 3
#define GDSM (NSTG * 2 * STAGE_B)

__device__ __forceinline__ void ldsm_x4(uint32_t& r0, uint32_t& r1, uint32_t& r2, uint32_t& r3, uint32_t a) {
    asm volatile("ldmatrix.sync.aligned.m8n8.x4.shared.b16 {%0,%1,%2,%3}, [%4];"
                 : "=r"(r0), "=r"(r1), "=r"(r2), "=r"(r3) : "r"(a));
}
__device__ __forceinline__ void ldsm_x2(uint32_t& r0, uint32_t& r1, uint32_t a) {
    asm volatile("ldmatrix.sync.aligned.m8n8.x2.shared.b16 {%0,%1}, [%2];"
                 : "=r"(r0), "=r"(r1) : "r"(a));
}
__device__ __forceinline__ void mma16816(float* d, const uint32_t* a, const uint32_t* b) {
    asm volatile("mma.sync.aligned.m16n8k16.row.col.f32.bf16.bf16.f32 "
                 "{%0,%1,%2,%3}, {%4,%5,%6,%7}, {%8,%9}, {%0,%1,%2,%3};"
                 : "+f"(d[0]), "+f"(d[1]), "+f"(d[2]), "+f"(d[3])
                 : "r"(a[0]), "r"(a[1]), "r"(a[2]), "r"(a[3]), "r"(b[0]), "r"(b[1]));
}

__global__ void __launch_bounds__(256) gemm_mma(
    const float* __restrict__ bout, float* __restrict__ out)
{
    extern __shared__ __align__(16) char dsm[];

    const int tid  = threadIdx.x;
    const int lane = tid & 31;
    const int wid  = tid >> 5;
    const int wm   = wid >> 2;
    const int wn   = wid & 3;
    const int ncol0 = blockIdx.x * 128;
    const int mrow0 = blockIdx.y * 128;

    const uint32_t smb = smem_u32(dsm);

    const int lrow = tid >> 1, lg2 = tid & 1;
    const __nv_bfloat16* gA = g_A3 + (size_t)(mrow0 + lrow) * 768 + lg2 * 16;
    const __nv_bfloat16* gB = g_B3 + (size_t)(ncol0 + lrow) * 768 + lg2 * 16;
    const uint32_t sAo = lrow * 80 + lg2 * 32;

    float acc[4][4][4] = {};

    #pragma unroll
    for (int p = 0; p < 2; p++) {
        uint32_t base = smb + p * 2 * STAGE_B;
        cpa16(base + sAo,      gA + p * 32);
        cpa16(base + sAo + 16, gA + p * 32 + 8);
        cpa16(base + STAGE_B + sAo,      gB + p * 32);
        cpa16(base + STAGE_B + sAo + 16, gB + p * 32 + 8);
        asm volatile("cp.async.commit_group;");
    }

    for (int c = 0; c < 24; c++) {
        if (c < 23) asm volatile("cp.async.wait_group 1;");
        else        asm volatile("cp.async.wait_group 0;");
        __syncthreads();
        if (c + 2 < 24) {
            const int s2 = (c + 2) % NSTG;
            const int ko = (c + 2) * 32;
            uint32_t base = smb + s2 * 2 * STAGE_B;
            cpa16(base + sAo,      gA + ko);
            cpa16(base + sAo + 16, gA + ko + 8);
            cpa16(base + STAGE_B + sAo,      gB + ko);
            cpa16(base + STAGE_B + sAo + 16, gB + ko + 8);
            asm volatile("cp.async.commit_group;");
        }
        const int s = c % NSTG;
        const uint32_t aBase = smb + s * 2 * STAGE_B;
        const uint32_t bBase = aBase + STAGE_B;
        #pragma unroll
        for (int s16 = 0; s16 < 2; s16++) {
            uint32_t a[4][4], b[4][2];
            #pragma unroll
            for (int mf = 0; mf < 4; mf++) {
                uint32_t addr = aBase + (wm * 64 + mf * 16 + (lane & 15)) * 80
                                       + (2 * s16 + (lane >> 4)) * 16;
                ldsm_x4(a[mf][0], a[mf][1], a[mf][2], a[mf][3], addr);
            }
            #pragma unroll
            for (int nf = 0; nf < 4; nf++) {
                uint32_t addr = bBase + (wn * 32 + nf * 8 + (lane & 7)) * 80
                                       + (2 * s16 + ((lane >> 3) & 1)) * 16;
                ldsm_x2(b[nf][0], b[nf][1], addr);
            }
            #pragma unroll
            for (int mf = 0; mf < 4; mf++)
                #pragma unroll
                for (int nf = 0; nf < 4; nf++)
                    mma16816(acc[mf][nf], a[mf], b[nf]);
        }
        __syncthreads();
    }

    #pragma unroll
    for (int mf = 0; mf < 4; mf++) {
        int r0 = mrow0 + wm * 64 + mf * 16 + (lane >> 2);
        int r1 = r0 + 8;
        #pragma unroll
        for (int nf = 0; nf < 4; nf++) {
            int gc = ncol0 + wn * 32 + nf * 8 + (lane & 3) * 2;
            float b0 = bout[gc], b1 = bout[gc + 1];
            if (r0 < MROWS) {
                float2 v = make_float2(acc[mf][nf][0] + b0, acc[mf][nf][1] + b1);
                *(float2*)&out[(size_t)r0 * VOC + gc] = v;
            }
            if (r1 < MROWS) {
                float2 v = make_float2(acc[mf][nf][2] + b0, acc[mf][nf][3] + b1);
                *(float2*)&out[(size_t)r1 * VOC + gc] = v;
            }
        }
    }
}

// ---------------- launch ----------------
extern "C" void kernel_launch(void* const* d_in, const int* in_sizes, int n_in,
                              void* d_out, int out_size)
{
    (void)in_sizes; (void)n_in; (void)out_size;
    const float* enc_key   = (const float*)d_in[0];
    const float* values    = (const float*)d_in[1];
    const int*   lens      = (const int*)  d_in[2];
    const int*   text      = (const int*)  d_in[3];
    const float* embedding = (const float*)d_in[4];
    const float* Wih1      = (const float*)d_in[5];
    const float* Whh1      = (const float*)d_in[6];
    const float* bih1      = (const float*)d_in[7];
    const float* bhh1      = (const float*)d_in[8];
    const float* Wih2      = (const float*)d_in[9];
    const float* Whh2      = (const float*)d_in[10];
    const float* bih2      = (const float*)d_in[11];
    const float* bhh2      = (const float*)d_in[12];
    const float* Wout      = (const float*)d_in[13];
    const float* bout      = (const float*)d_in[14];
    float* out = (float*)d_out;

    cudaFuncSetAttribute(gemm_mma, cudaFuncAttributeMaxDynamicSharedMemorySize, GDSM);

    convB<<<8000, 256>>>(Wout);
    decoder_persist<<<NBLK, 256>>>(enc_key, values, lens, text, embedding,
                                   Wih1, Whh1, bih1, bhh1,
                                   Wih2, Whh2, bih2, bhh2, out);
    convA<<<1600, 256>>>();
    gemm_mma<<<dim3(250, 50), 256, GDSM>>>(bout, out);
}